// round 4
// baseline (speedup 1.0000x reference)
#include <cuda_runtime.h>
#include <cuda_bf16.h>
#include <stdint.h>
#include <math.h>

#define NN   8192
#define EMB  128
#define KL   3
#define NKE  (KL * EMB)   // 384

// ---------------- persistent scratch (no allocations allowed) ----------------
__device__ __nv_bfloat16 g_Ahi[(size_t)NN * NN];     // 128 MB
__device__ __nv_bfloat16 g_Alo[(size_t)NN * NN];     // 128 MB
__device__ __nv_bfloat16 g_Wph[(size_t)NN * NKE];
__device__ __nv_bfloat16 g_Wpl[(size_t)NN * NKE];
__device__ __nv_bfloat16 g_Wqh[(size_t)NN * NKE];
__device__ __nv_bfloat16 g_Wql[(size_t)NN * NKE];
__device__ float         g_dec [(size_t)NN * EMB];
__device__ __nv_bfloat16 g_dech[(size_t)NN * EMB];
__device__ __nv_bfloat16 g_decl[(size_t)NN * EMB];
__device__ __nv_bfloat16 g_qh  [(size_t)NN * EMB];
__device__ __nv_bfloat16 g_ql  [(size_t)NN * EMB];
__device__ float g_Dout[NN];
__device__ float g_Din [NN];

// ---------------- degree kernels ----------------
__global__ void zero_dout_kernel() {
    int i = blockIdx.x * blockDim.x + threadIdx.x;
    if (i < NN) g_Dout[i] = 0.0f;
}

__global__ void colsum_kernel(const float* __restrict__ A) {
    int j = blockIdx.x * blockDim.x + threadIdx.x;
    int chunk = NN / gridDim.y;
    int i0 = blockIdx.y * chunk;
    float s0 = 0.f, s1 = 0.f, s2 = 0.f, s3 = 0.f;
    for (int i = i0; i < i0 + chunk; i += 4) {
        s0 += A[(size_t)(i + 0) * NN + j];
        s1 += A[(size_t)(i + 1) * NN + j];
        s2 += A[(size_t)(i + 2) * NN + j];
        s3 += A[(size_t)(i + 3) * NN + j];
    }
    atomicAdd(&g_Dout[j], (s0 + s1) + (s2 + s3));
}

__global__ void rowsum_kernel(const float* __restrict__ A) {
    int row  = blockIdx.x * (blockDim.x >> 5) + (threadIdx.x >> 5);
    int lane = threadIdx.x & 31;
    const float4* Ar = (const float4*)(A + (size_t)row * NN);
    float s = 0.f;
    for (int i = lane; i < NN / 4; i += 32) {
        float4 v = Ar[i];
        s += (v.x + v.y) + (v.z + v.w);
    }
    #pragma unroll
    for (int o = 16; o; o >>= 1) s += __shfl_xor_sync(0xFFFFFFFFu, s, o);
    if (lane == 0) g_Din[row] = s;
}

// ---------------- fp32 -> bf16 hi/lo split ----------------
__global__ void split_kernel(const float* __restrict__ X,
                             __nv_bfloat16* __restrict__ H,
                             __nv_bfloat16* __restrict__ L) {
    size_t i = ((size_t)blockIdx.x * blockDim.x + threadIdx.x) * 4;
    float4 v = *(const float4*)(X + i);
    float vv[4] = {v.x, v.y, v.z, v.w};
    __nv_bfloat16 h[4], l[4];
    #pragma unroll
    for (int j = 0; j < 4; j++) {
        h[j] = __float2bfloat16(vv[j]);
        l[j] = __float2bfloat16(vv[j] - __bfloat162float(h[j]));
    }
    *(uint2*)&H[i] = *(uint2*)h;
    *(uint2*)&L[i] = *(uint2*)l;
}

// ---------------- small fp32 GEMM (projections + dec) ----------------
// C(m,n) = sum_k A(m,k)*B(n,k)  (both row-major, k contiguous)
// EPI 2: +bias, store fp32 C[m*ldc+n]
// EPI 4: +bias, split to bf16 hi/lo at OH/OL[m*ldc+n]
template<int EPI>
__global__ void __launch_bounds__(256)
sgemm_small(const float* __restrict__ A, const float* __restrict__ B,
            float* __restrict__ C, int Kdim, int ldc,
            const float* __restrict__ bias,
            __nv_bfloat16* __restrict__ OH, __nv_bfloat16* __restrict__ OL)
{
    constexpr int BM = 64, BN = 64, BK = 16;
    __shared__ float As[BK][BM + 4];
    __shared__ float Bs[BK][BN + 4];
    const int t  = threadIdx.x;
    const int tx = t & 15, ty = t >> 4;
    const int m0 = blockIdx.y * BM, n0 = blockIdx.x * BN;

    float acc[4][4];
    #pragma unroll
    for (int i = 0; i < 4; i++)
        #pragma unroll
        for (int j = 0; j < 4; j++) acc[i][j] = 0.f;

    for (int k0 = 0; k0 < Kdim; k0 += BK) {
        { // A tile (m-major, k contiguous) -> transpose into As[k][m]
            const int mm = t >> 2, kk = (t & 3) << 2;
            float4 v = *(const float4*)&A[(size_t)(m0 + mm) * Kdim + (k0 + kk)];
            As[kk + 0][mm] = v.x; As[kk + 1][mm] = v.y;
            As[kk + 2][mm] = v.z; As[kk + 3][mm] = v.w;
        }
        { // B tile (n-major, k contiguous) -> Bs[k][n]
            const int nn = t >> 2, kk = (t & 3) << 2;
            float4 v = *(const float4*)&B[(size_t)(n0 + nn) * Kdim + (k0 + kk)];
            Bs[kk + 0][nn] = v.x; Bs[kk + 1][nn] = v.y;
            Bs[kk + 2][nn] = v.z; Bs[kk + 3][nn] = v.w;
        }
        __syncthreads();
        #pragma unroll
        for (int kk = 0; kk < BK; kk++) {
            float4 av = *(const float4*)&As[kk][ty << 2];
            float4 bv = *(const float4*)&Bs[kk][tx << 2];
            float a4[4] = {av.x, av.y, av.z, av.w};
            float b4[4] = {bv.x, bv.y, bv.z, bv.w};
            #pragma unroll
            for (int i = 0; i < 4; i++)
                #pragma unroll
                for (int j = 0; j < 4; j++) acc[i][j] += a4[i] * b4[j];
        }
        __syncthreads();
    }

    #pragma unroll
    for (int i = 0; i < 4; i++) {
        const int m = m0 + (ty << 2) + i;
        const int n = n0 + (tx << 2);
        float r[4];
        #pragma unroll
        for (int j = 0; j < 4; j++) r[j] = acc[i][j] + bias[n + j];
        if (EPI == 2) {
            *(float4*)&C[(size_t)m * ldc + n] = make_float4(r[0], r[1], r[2], r[3]);
        } else {
            __nv_bfloat16 h[4], l[4];
            #pragma unroll
            for (int j = 0; j < 4; j++) {
                h[j] = __float2bfloat16(r[j]);
                l[j] = __float2bfloat16(r[j] - __bfloat162float(h[j]));
            }
            *(uint2*)&OH[(size_t)m * ldc + n] = *(uint2*)h;
            *(uint2*)&OL[(size_t)m * ldc + n] = *(uint2*)l;
        }
    }
}

// ---------------- tensor-core bf16 split-precision GEMM ----------------
__device__ __forceinline__ void mma16816(float* c, const uint32_t* a, const uint32_t* b) {
    asm volatile(
        "mma.sync.aligned.m16n8k16.row.col.f32.bf16.bf16.f32 "
        "{%0,%1,%2,%3}, {%4,%5,%6,%7}, {%8,%9}, {%0,%1,%2,%3};\n"
        : "+f"(c[0]), "+f"(c[1]), "+f"(c[2]), "+f"(c[3])
        : "r"(a[0]), "r"(a[1]), "r"(a[2]), "r"(a[3]), "r"(b[0]), "r"(b[1]));
}

// C(m,n) = sum_k A(m,k)*B(n,k) with A,B given as bf16 hi/lo arrays.
// TA: A global is k-major (As[m][k] = A[k*lda + m]); else m-major (A[m*lda + k])
// TB: same for B rows n.
// EPI 1: v/deg[m], leaky_relu(0.01), store [K,N,D] remap (n = layer*128+e)
// EPI 3: v * a*d^b*exp(c*d), d = dist[m*NN+n], store C[m*NN+n]
template<bool TA, bool TB, int EPI>
__global__ void __launch_bounds__(256)
mma_gemm(const __nv_bfloat16* __restrict__ Ah, const __nv_bfloat16* __restrict__ Al, int lda,
         const __nv_bfloat16* __restrict__ Bh, const __nv_bfloat16* __restrict__ Bl, int ldb,
         float* __restrict__ C, int Kdim,
         const float* __restrict__ deg,
         const float* __restrict__ dist,
         const float* __restrict__ sa, const float* __restrict__ sb,
         const float* __restrict__ sc)
{
    constexpr int BM = 128, BN = 128, BK = 32, LDS_ = 40;
    __shared__ __align__(16) __nv_bfloat16 sAh[BM * LDS_];
    __shared__ __align__(16) __nv_bfloat16 sAl[BM * LDS_];
    __shared__ __align__(16) __nv_bfloat16 sBh[BN * LDS_];
    __shared__ __align__(16) __nv_bfloat16 sBl[BN * LDS_];

    const int tid  = threadIdx.x;
    const int wid  = tid >> 5, lane = tid & 31;
    const int g    = lane >> 2, t = lane & 3;
    const int wm   = (wid >> 1) * 32;   // 4 warps in m
    const int wn   = (wid & 1) * 64;    // 2 warps in n
    const int m0   = blockIdx.y * BM;
    const int n0   = blockIdx.x * BN;

    float acc[2][8][4];
    #pragma unroll
    for (int mi = 0; mi < 2; mi++)
        #pragma unroll
        for (int ni = 0; ni < 8; ni++)
            #pragma unroll
            for (int r = 0; r < 4; r++) acc[mi][ni][r] = 0.f;

    for (int k0 = 0; k0 < Kdim; k0 += BK) {
        // ---- load A tiles (hi & lo) ----
        if (!TA) {
            #pragma unroll
            for (int it = 0; it < 2; it++) {
                int lin = tid + it * 256;          // 0..511
                int r = lin >> 2, cg = lin & 3;
                *(uint4*)&sAh[r * LDS_ + cg * 8] =
                    *(const uint4*)&Ah[(size_t)(m0 + r) * lda + k0 + cg * 8];
                *(uint4*)&sAl[r * LDS_ + cg * 8] =
                    *(const uint4*)&Al[(size_t)(m0 + r) * lda + k0 + cg * 8];
            }
        } else {
            #pragma unroll
            for (int it = 0; it < 2; it++) {
                int lin = tid + it * 256;
                int k = lin >> 4, mg = lin & 15;
                uint4 vh = *(const uint4*)&Ah[(size_t)(k0 + k) * lda + m0 + mg * 8];
                uint4 vl = *(const uint4*)&Al[(size_t)(k0 + k) * lda + m0 + mg * 8];
                __nv_bfloat16 eh[8], el[8];
                *(uint4*)eh = vh; *(uint4*)el = vl;
                #pragma unroll
                for (int j = 0; j < 8; j++) {
                    sAh[(mg * 8 + j) * LDS_ + k] = eh[j];
                    sAl[(mg * 8 + j) * LDS_ + k] = el[j];
                }
            }
        }
        // ---- load B tiles (hi & lo) ----
        if (!TB) {
            #pragma unroll
            for (int it = 0; it < 2; it++) {
                int lin = tid + it * 256;
                int r = lin >> 2, cg = lin & 3;
                *(uint4*)&sBh[r * LDS_ + cg * 8] =
                    *(const uint4*)&Bh[(size_t)(n0 + r) * ldb + k0 + cg * 8];
                *(uint4*)&sBl[r * LDS_ + cg * 8] =
                    *(const uint4*)&Bl[(size_t)(n0 + r) * ldb + k0 + cg * 8];
            }
        } else {
            #pragma unroll
            for (int it = 0; it < 2; it++) {
                int lin = tid + it * 256;
                int k = lin >> 4, ng = lin & 15;
                uint4 vh = *(const uint4*)&Bh[(size_t)(k0 + k) * ldb + n0 + ng * 8];
                uint4 vl = *(const uint4*)&Bl[(size_t)(k0 + k) * ldb + n0 + ng * 8];
                __nv_bfloat16 eh[8], el[8];
                *(uint4*)eh = vh; *(uint4*)el = vl;
                #pragma unroll
                for (int j = 0; j < 8; j++) {
                    sBh[(ng * 8 + j) * LDS_ + k] = eh[j];
                    sBl[(ng * 8 + j) * LDS_ + k] = el[j];
                }
            }
        }
        __syncthreads();

        #pragma unroll
        for (int kk = 0; kk < BK; kk += 16) {
            uint32_t ah[2][4], al[2][4], bh[8][2], bl[8][2];
            const int kb = kk + 2 * t;
            #pragma unroll
            for (int mi = 0; mi < 2; mi++) {
                const int r0 = wm + mi * 16 + g;
                ah[mi][0] = *(const uint32_t*)&sAh[(r0    ) * LDS_ + kb    ];
                ah[mi][1] = *(const uint32_t*)&sAh[(r0 + 8) * LDS_ + kb    ];
                ah[mi][2] = *(const uint32_t*)&sAh[(r0    ) * LDS_ + kb + 8];
                ah[mi][3] = *(const uint32_t*)&sAh[(r0 + 8) * LDS_ + kb + 8];
                al[mi][0] = *(const uint32_t*)&sAl[(r0    ) * LDS_ + kb    ];
                al[mi][1] = *(const uint32_t*)&sAl[(r0 + 8) * LDS_ + kb    ];
                al[mi][2] = *(const uint32_t*)&sAl[(r0    ) * LDS_ + kb + 8];
                al[mi][3] = *(const uint32_t*)&sAl[(r0 + 8) * LDS_ + kb + 8];
            }
            #pragma unroll
            for (int ni = 0; ni < 8; ni++) {
                const int nr = wn + ni * 8 + g;
                bh[ni][0] = *(const uint32_t*)&sBh[nr * LDS_ + kb    ];
                bh[ni][1] = *(const uint32_t*)&sBh[nr * LDS_ + kb + 8];
                bl[ni][0] = *(const uint32_t*)&sBl[nr * LDS_ + kb    ];
                bl[ni][1] = *(const uint32_t*)&sBl[nr * LDS_ + kb + 8];
            }
            #pragma unroll
            for (int mi = 0; mi < 2; mi++)
                #pragma unroll
                for (int ni = 0; ni < 8; ni++) {
                    mma16816(acc[mi][ni], ah[mi], bh[ni]);  // hi*hi
                    mma16816(acc[mi][ni], ah[mi], bl[ni]);  // hi*lo
                    mma16816(acc[mi][ni], al[mi], bh[ni]);  // lo*hi
                }
        }
        __syncthreads();
    }

    // ---------------- epilogue ----------------
    float sa0 = 0.f, sb0 = 0.f, sc0 = 0.f;
    if (EPI == 3) { sa0 = *sa; sb0 = *sb; sc0 = *sc; }

    #pragma unroll
    for (int mi = 0; mi < 2; mi++) {
        const int mA = m0 + wm + mi * 16 + g;
        const int mB = mA + 8;
        float dA = 0.f, dB = 0.f;
        if (EPI == 1) { dA = deg[mA]; dB = deg[mB]; }
        #pragma unroll
        for (int ni = 0; ni < 8; ni++) {
            const int n = n0 + wn + ni * 8 + 2 * t;
            float c0 = acc[mi][ni][0], c1 = acc[mi][ni][1];
            float c2 = acc[mi][ni][2], c3 = acc[mi][ni][3];
            if (EPI == 1) {
                c0 /= dA; c1 /= dA; c2 /= dB; c3 /= dB;
                c0 = (c0 > 0.f) ? c0 : 0.01f * c0;
                c1 = (c1 > 0.f) ? c1 : 0.01f * c1;
                c2 = (c2 > 0.f) ? c2 : 0.01f * c2;
                c3 = (c3 > 0.f) ? c3 : 0.01f * c3;
                const size_t base = (size_t)(n >> 7) * ((size_t)NN * EMB) + (n & 127);
                *(float2*)&C[base + (size_t)mA * EMB] = make_float2(c0, c1);
                *(float2*)&C[base + (size_t)mB * EMB] = make_float2(c2, c3);
            } else { // EPI == 3
                float2 d0 = *(const float2*)&dist[(size_t)mA * NN + n];
                float2 d1 = *(const float2*)&dist[(size_t)mB * NN + n];
                float f0 = sa0 * __powf(d0.x, sb0) * __expf(sc0 * d0.x);
                float f1 = sa0 * __powf(d0.y, sb0) * __expf(sc0 * d0.y);
                float f2 = sa0 * __powf(d1.x, sb0) * __expf(sc0 * d1.x);
                float f3 = sa0 * __powf(d1.y, sb0) * __expf(sc0 * d1.y);
                *(float2*)&C[(size_t)mA * NN + n] = make_float2(c0 * f0, c1 * f1);
                *(float2*)&C[(size_t)mB * NN + n] = make_float2(c2 * f2, c3 * f3);
            }
        }
    }
}

// ---------------- launcher ----------------
extern "C" void kernel_launch(void* const* d_in, const int* in_sizes, int n_in,
                              void* d_out, int out_size)
{
    const float* p    = (const float*)d_in[0];
    const float* q    = (const float*)d_in[1];
    const float* A    = (const float*)d_in[2];
    const float* dist = (const float*)d_in[3];
    const float* Ws   = (const float*)d_in[4];
    const float* bs   = (const float*)d_in[5];
    const float* Wd   = (const float*)d_in[6];
    const float* bd   = (const float*)d_in[7];
    const float* a    = (const float*)d_in[8];
    const float* b    = (const float*)d_in[9];
    const float* c    = (const float*)d_in[10];

    float* out   = (float*)d_out;
    float* out_p = out;
    float* out_q = out   + (size_t)KL * NN * EMB;
    float* out_e = out_q + (size_t)KL * NN * EMB;

    __nv_bfloat16 *ahi, *alo, *wph, *wpl, *wqh, *wql, *dch, *dcl, *qh, *ql;
    float *dec, *dout, *din;
    cudaGetSymbolAddress((void**)&ahi, g_Ahi);
    cudaGetSymbolAddress((void**)&alo, g_Alo);
    cudaGetSymbolAddress((void**)&wph, g_Wph);
    cudaGetSymbolAddress((void**)&wpl, g_Wpl);
    cudaGetSymbolAddress((void**)&wqh, g_Wqh);
    cudaGetSymbolAddress((void**)&wql, g_Wql);
    cudaGetSymbolAddress((void**)&dch, g_dech);
    cudaGetSymbolAddress((void**)&dcl, g_decl);
    cudaGetSymbolAddress((void**)&qh,  g_qh);
    cudaGetSymbolAddress((void**)&ql,  g_ql);
    cudaGetSymbolAddress((void**)&dec, g_dec);
    cudaGetSymbolAddress((void**)&dout, g_Dout);
    cudaGetSymbolAddress((void**)&din,  g_Din);

    // degrees
    zero_dout_kernel<<<NN / 256, 256>>>();
    colsum_kernel<<<dim3(NN / 256, 8), 256>>>(A);
    rowsum_kernel<<<NN / 8, 256>>>(A);

    // split adjacency into bf16 hi/lo (done once per launch, reused by 2 GEMMs)
    split_kernel<<<(int)(((size_t)NN * NN / 4) / 256), 256>>>(A, ahi, alo);

    // projections: Wp/Wq [i, k*128+e] = inputs @ Ws^T (+bs), emitted as bf16 hi/lo
    sgemm_small<4><<<dim3(NKE / 64, NN / 64), 256>>>(p, Ws, nullptr, EMB, NKE, bs, wph, wpl);
    sgemm_small<4><<<dim3(NKE / 64, NN / 64), 256>>>(q, Ws, nullptr, EMB, NKE, bs, wqh, wql);

    // p_k = leaky_relu( (A^T @ Wp) / D_out[j] )  -> out_p [K,N,D]
    mma_gemm<true, true, 1><<<dim3(NKE / 128, NN / 128), 256>>>(
        ahi, alo, NN, wph, wpl, NKE, out_p, NN, dout, nullptr, nullptr, nullptr, nullptr);
    // q_k = leaky_relu( (A @ Wq) / D_in[j] )     -> out_q [K,N,D]
    mma_gemm<false, true, 1><<<dim3(NKE / 128, NN / 128), 256>>>(
        ahi, alo, NN, wqh, wql, NKE, out_q, NN, din, nullptr, nullptr, nullptr, nullptr);

    // dec = p_k[-1] @ Wd^T + bd  (fp32, small)
    const float* pk2 = out_p + (size_t)(KL - 1) * NN * EMB;
    sgemm_small<2><<<dim3(EMB / 64, NN / 64), 256>>>(pk2, Wd, dec, EMB, EMB, bd, nullptr, nullptr);

    // split dec and q_k[-1] to bf16 hi/lo
    const float* qk2 = out_q + (size_t)(KL - 1) * NN * EMB;
    split_kernel<<<(int)(((size_t)NN * EMB / 4) / 256), 256>>>(dec, dch, dcl);
    split_kernel<<<(int)(((size_t)NN * EMB / 4) / 256), 256>>>(qk2, qh, ql);

    // e_ij = (dec @ q_k[-1]^T) * a*d^b*exp(c*d)
    mma_gemm<false, false, 3><<<dim3(NN / 128, NN / 128), 256>>>(
        dch, dcl, EMB, qh, ql, EMB, out_e, EMB, nullptr, dist, a, b, c);
}

// round 5
// speedup vs baseline: 3.1860x; 3.1860x over previous
#include <cuda_runtime.h>
#include <cuda_bf16.h>
#include <stdint.h>
#include <math.h>

#define NN   8192
#define EMB  128
#define KL   3
#define NKE  (KL * EMB)   // 384

// ---------------- persistent scratch (no allocations allowed) ----------------
__device__ __align__(16) __nv_bfloat16 g_Ahi [(size_t)NN * NN];   // A row-major hi
__device__ __align__(16) __nv_bfloat16 g_Alo [(size_t)NN * NN];   // A row-major lo
__device__ __align__(16) __nv_bfloat16 g_AThi[(size_t)NN * NN];   // A^T hi
__device__ __align__(16) __nv_bfloat16 g_ATlo[(size_t)NN * NN];   // A^T lo
__device__ __align__(16) __nv_bfloat16 g_Wph[(size_t)NKE * NN];   // Wp^T [e][i] hi
__device__ __align__(16) __nv_bfloat16 g_Wpl[(size_t)NKE * NN];
__device__ __align__(16) __nv_bfloat16 g_Wqh[(size_t)NKE * NN];
__device__ __align__(16) __nv_bfloat16 g_Wql[(size_t)NKE * NN];
__device__ __align__(16) __nv_bfloat16 g_dech[(size_t)NN * EMB];
__device__ __align__(16) __nv_bfloat16 g_decl[(size_t)NN * EMB];
__device__ __align__(16) __nv_bfloat16 g_qh  [(size_t)NN * EMB];
__device__ __align__(16) __nv_bfloat16 g_ql  [(size_t)NN * EMB];
__device__ float g_Dout[NN];
__device__ float g_Din [NN];

// ---------------- helpers ----------------
__device__ __forceinline__ void cp16(uint32_t dst_smem, const void* src) {
    asm volatile("cp.async.ca.shared.global [%0], [%1], 16;\n"
                 :: "r"(dst_smem), "l"(src));
}
__device__ __forceinline__ void mma16816(float* c, const uint32_t* a, const uint32_t* b) {
    asm volatile(
        "mma.sync.aligned.m16n8k16.row.col.f32.bf16.bf16.f32 "
        "{%0,%1,%2,%3}, {%4,%5,%6,%7}, {%8,%9}, {%0,%1,%2,%3};\n"
        : "+f"(c[0]), "+f"(c[1]), "+f"(c[2]), "+f"(c[3])
        : "r"(a[0]), "r"(a[1]), "r"(a[2]), "r"(a[3]), "r"(b[0]), "r"(b[1]));
}

__global__ void zero_deg_kernel() {
    int i = blockIdx.x * blockDim.x + threadIdx.x;
    if (i < NN) { g_Dout[i] = 0.0f; g_Din[i] = 0.0f; }
}

// ---------------- prep: A -> bf16 hi/lo (row-major + transposed) + degrees ----------------
// grid (NN/64, NN/64), block 256. Tile 64x64.
__global__ void __launch_bounds__(256) prep_kernel(const float* __restrict__ A) {
    __shared__ float tile[64][65];
    const int bi = blockIdx.y * 64;   // i (row) base
    const int bj = blockIdx.x * 64;   // j (col) base
    const int tid = threadIdx.x;
    const int r  = tid >> 2;          // 0..63
    const int cs = tid & 3;           // 0..3 : 16-element segment

    // phase 1: read 16 floats of row (bi+r), cols bj+cs*16..+15
    const float* src = A + (size_t)(bi + r) * NN + bj + cs * 16;
    float v[16];
    #pragma unroll
    for (int u = 0; u < 4; u++) {
        float4 f = *(const float4*)(src + u * 4);
        v[u*4+0] = f.x; v[u*4+1] = f.y; v[u*4+2] = f.z; v[u*4+3] = f.w;
    }
    // row-major hi/lo store
    __align__(16) __nv_bfloat16 h[16], l[16];
    float rs = 0.f;
    #pragma unroll
    for (int u = 0; u < 16; u++) {
        h[u] = __float2bfloat16(v[u]);
        l[u] = __float2bfloat16(v[u] - __bfloat162float(h[u]));
        tile[r][cs * 16 + u] = v[u];
        rs += v[u];
    }
    {
        size_t idx = (size_t)(bi + r) * NN + bj + cs * 16;
        *(uint4*)&g_Ahi[idx]     = *(uint4*)&h[0];
        *(uint4*)&g_Ahi[idx + 8] = *(uint4*)&h[8];
        *(uint4*)&g_Alo[idx]     = *(uint4*)&l[0];
        *(uint4*)&g_Alo[idx + 8] = *(uint4*)&l[8];
    }
    // D_in[i] = sum_j A[i][j] : reduce 4 segments
    rs += __shfl_xor_sync(0xFFFFFFFFu, rs, 1);
    rs += __shfl_xor_sync(0xFFFFFFFFu, rs, 2);
    if (cs == 0) atomicAdd(&g_Din[bi + r], rs);

    __syncthreads();

    // phase 2: transposed row jj = r (j index), i segment cs*16..+15
    float csum = 0.f;
    #pragma unroll
    for (int u = 0; u < 16; u++) {
        float w = tile[cs * 16 + u][r];
        h[u] = __float2bfloat16(w);
        l[u] = __float2bfloat16(w - __bfloat162float(h[u]));
        csum += w;
    }
    {
        size_t idx = (size_t)(bj + r) * NN + bi + cs * 16;
        *(uint4*)&g_AThi[idx]     = *(uint4*)&h[0];
        *(uint4*)&g_AThi[idx + 8] = *(uint4*)&h[8];
        *(uint4*)&g_ATlo[idx]     = *(uint4*)&l[0];
        *(uint4*)&g_ATlo[idx + 8] = *(uint4*)&l[8];
    }
    // D_out[j] = sum_i A[i][j]
    csum += __shfl_xor_sync(0xFFFFFFFFu, csum, 1);
    csum += __shfl_xor_sync(0xFFFFFFFFu, csum, 2);
    if (cs == 0) atomicAdd(&g_Dout[bj + r], csum);
}

// ---------------- small fp32 GEMM ----------------
// C(m,n) = sum_k A(m,k)*B(n,k), both row-major (k contiguous).
// EPI 0 (proj): +bias[n], store TRANSPOSED bf16 hi/lo: OH/OL[n*NN + m]
// EPI 1 (dec):  +bias[n], store row-major bf16 hi/lo:  OH/OL[m*EMB + n]
template<int EPI>
__global__ void __launch_bounds__(256)
sgemm_small(const float* __restrict__ A, const float* __restrict__ B,
            int Kdim, const float* __restrict__ bias,
            __nv_bfloat16* __restrict__ OH, __nv_bfloat16* __restrict__ OL)
{
    constexpr int BM = 64, BN = 64, BK = 16;
    __shared__ float As[BK][BM + 4];
    __shared__ float Bs[BK][BN + 4];
    const int t  = threadIdx.x;
    const int tx = t & 15, ty = t >> 4;
    const int m0 = blockIdx.y * BM, n0 = blockIdx.x * BN;

    float acc[4][4];
    #pragma unroll
    for (int i = 0; i < 4; i++)
        #pragma unroll
        for (int j = 0; j < 4; j++) acc[i][j] = 0.f;

    for (int k0 = 0; k0 < Kdim; k0 += BK) {
        {
            const int mm = t >> 2, kk = (t & 3) << 2;
            float4 v = *(const float4*)&A[(size_t)(m0 + mm) * Kdim + (k0 + kk)];
            As[kk + 0][mm] = v.x; As[kk + 1][mm] = v.y;
            As[kk + 2][mm] = v.z; As[kk + 3][mm] = v.w;
        }
        {
            const int nn = t >> 2, kk = (t & 3) << 2;
            float4 v = *(const float4*)&B[(size_t)(n0 + nn) * Kdim + (k0 + kk)];
            Bs[kk + 0][nn] = v.x; Bs[kk + 1][nn] = v.y;
            Bs[kk + 2][nn] = v.z; Bs[kk + 3][nn] = v.w;
        }
        __syncthreads();
        #pragma unroll
        for (int kk = 0; kk < BK; kk++) {
            float4 av = *(const float4*)&As[kk][ty << 2];
            float4 bv = *(const float4*)&Bs[kk][tx << 2];
            float a4[4] = {av.x, av.y, av.z, av.w};
            float b4[4] = {bv.x, bv.y, bv.z, bv.w};
            #pragma unroll
            for (int i = 0; i < 4; i++)
                #pragma unroll
                for (int j = 0; j < 4; j++) acc[i][j] += a4[i] * b4[j];
        }
        __syncthreads();
    }

    if (EPI == 0) {
        // transposed store: for each n, 4 consecutive m values -> uint2
        #pragma unroll
        for (int j = 0; j < 4; j++) {
            const int n = n0 + (tx << 2) + j;
            const float bn = bias[n];
            __align__(8) __nv_bfloat16 h[4], l[4];
            #pragma unroll
            for (int i = 0; i < 4; i++) {
                float r = acc[i][j] + bn;
                h[i] = __float2bfloat16(r);
                l[i] = __float2bfloat16(r - __bfloat162float(h[i]));
            }
            size_t idx = (size_t)n * NN + m0 + (ty << 2);
            *(uint2*)&OH[idx] = *(uint2*)h;
            *(uint2*)&OL[idx] = *(uint2*)l;
        }
    } else {
        #pragma unroll
        for (int i = 0; i < 4; i++) {
            const int m = m0 + (ty << 2) + i;
            const int n = n0 + (tx << 2);
            __align__(8) __nv_bfloat16 h[4], l[4];
            #pragma unroll
            for (int j = 0; j < 4; j++) {
                float r = acc[i][j] + bias[n + j];
                h[j] = __float2bfloat16(r);
                l[j] = __float2bfloat16(r - __bfloat162float(h[j]));
            }
            size_t idx = (size_t)m * EMB + n;
            *(uint2*)&OH[idx] = *(uint2*)h;
            *(uint2*)&OL[idx] = *(uint2*)l;
        }
    }
}

// ---------------- tensor-core split-precision GEMM (cp.async, 2-stage) ----------------
// C(m,n) = sum_k A(m,k)*B(n,k); A m-major [M x Kdim] (lda), B n-major [Nn x Kdim] (ldb).
// Tiles: BM=128, BN=64, BK=32.
// EPI 1: v/deg[m], leaky_relu, store [K,N,D] remap; if OH!=null and layer==KL-1,
//        also store bf16 hi/lo at OH/OL[m*EMB + (n&127)].
// EPI 3: v * a*d^b*exp(c*d), d = dist[m*NN+n], store C[m*NN+n].
#define STG_STRIDE 30720
#define SMEM_BYTES (2 * STG_STRIDE)

template<int EPI>
__global__ void __launch_bounds__(256)
mma_gemm(const __nv_bfloat16* __restrict__ Ah, const __nv_bfloat16* __restrict__ Al, int lda,
         const __nv_bfloat16* __restrict__ Bh, const __nv_bfloat16* __restrict__ Bl, int ldb,
         float* __restrict__ C, int Kdim,
         const float* __restrict__ deg,
         const float* __restrict__ dist,
         const float* __restrict__ sa, const float* __restrict__ sb,
         const float* __restrict__ sc,
         __nv_bfloat16* __restrict__ OH, __nv_bfloat16* __restrict__ OL)
{
    extern __shared__ __align__(16) char smem[];
    const uint32_t sbase = (uint32_t)__cvta_generic_to_shared(smem);

    const int tid  = threadIdx.x;
    const int wid  = tid >> 5, lane = tid & 31;
    const int g    = lane >> 2, t4 = lane & 3;
    const int wm   = (wid >> 1) * 32;   // 4 warps in m (128)
    const int wn   = (wid & 1) * 32;    // 2 warps in n (64)
    const int m0   = blockIdx.y * 128;
    const int n0   = blockIdx.x * 64;

    // per-thread copy coordinates
    const int arow0 = tid >> 2;          // 0..63 (A uses +0 and +256 -> rows 0..127)
    const int aseg  = (tid & 3) * 16;    // byte seg within 64B row (BK=32 bf16)
    const int asege = (tid & 3) * 8;     // element seg

    float acc[2][4][4];
    #pragma unroll
    for (int mi = 0; mi < 2; mi++)
        #pragma unroll
        for (int ni = 0; ni < 4; ni++)
            #pragma unroll
            for (int r = 0; r < 4; r++) acc[mi][ni][r] = 0.f;

    const int T = Kdim / 32;

    // --- async tile issue ---
    auto issue = [&](int k0, int s) {
        uint32_t sb = sbase + s * STG_STRIDE;
        #pragma unroll
        for (int it = 0; it < 2; it++) {
            int row = arow0 + it * 64;
            uint32_t dst = sb + row * 80 + aseg;
            cp16(dst,         &Ah[(size_t)(m0 + row) * lda + k0 + asege]);
            cp16(dst + 10240, &Al[(size_t)(m0 + row) * lda + k0 + asege]);
        }
        {
            int row = arow0;
            uint32_t dst = sb + 20480 + row * 80 + aseg;
            cp16(dst,        &Bh[(size_t)(n0 + row) * ldb + k0 + asege]);
            cp16(dst + 5120, &Bl[(size_t)(n0 + row) * ldb + k0 + asege]);
        }
        asm volatile("cp.async.commit_group;\n" ::: "memory");
    };

    issue(0, 0);

    for (int it = 0; it < T; it++) {
        if (it + 1 < T) {
            issue((it + 1) * 32, (it + 1) & 1);
            asm volatile("cp.async.wait_group 1;\n" ::: "memory");
        } else {
            asm volatile("cp.async.wait_group 0;\n" ::: "memory");
        }
        __syncthreads();

        const int s = it & 1;
        const __nv_bfloat16* pAh = (const __nv_bfloat16*)(smem + s * STG_STRIDE);
        const __nv_bfloat16* pAl = (const __nv_bfloat16*)(smem + s * STG_STRIDE + 10240);
        const __nv_bfloat16* pBh = (const __nv_bfloat16*)(smem + s * STG_STRIDE + 20480);
        const __nv_bfloat16* pBl = (const __nv_bfloat16*)(smem + s * STG_STRIDE + 25600);

        #pragma unroll
        for (int kk = 0; kk < 32; kk += 16) {
            const int kb = kk + 2 * t4;
            uint32_t ah[2][4], al[2][4], bh[4][2], bl[4][2];
            #pragma unroll
            for (int mi = 0; mi < 2; mi++) {
                const int r0 = wm + mi * 16 + g;
                ah[mi][0] = *(const uint32_t*)&pAh[(r0    ) * 40 + kb    ];
                ah[mi][1] = *(const uint32_t*)&pAh[(r0 + 8) * 40 + kb    ];
                ah[mi][2] = *(const uint32_t*)&pAh[(r0    ) * 40 + kb + 8];
                ah[mi][3] = *(const uint32_t*)&pAh[(r0 + 8) * 40 + kb + 8];
                al[mi][0] = *(const uint32_t*)&pAl[(r0    ) * 40 + kb    ];
                al[mi][1] = *(const uint32_t*)&pAl[(r0 + 8) * 40 + kb    ];
                al[mi][2] = *(const uint32_t*)&pAl[(r0    ) * 40 + kb + 8];
                al[mi][3] = *(const uint32_t*)&pAl[(r0 + 8) * 40 + kb + 8];
            }
            #pragma unroll
            for (int ni = 0; ni < 4; ni++) {
                const int nr = wn + ni * 8 + g;
                bh[ni][0] = *(const uint32_t*)&pBh[nr * 40 + kb    ];
                bh[ni][1] = *(const uint32_t*)&pBh[nr * 40 + kb + 8];
                bl[ni][0] = *(const uint32_t*)&pBl[nr * 40 + kb    ];
                bl[ni][1] = *(const uint32_t*)&pBl[nr * 40 + kb + 8];
            }
            #pragma unroll
            for (int mi = 0; mi < 2; mi++)
                #pragma unroll
                for (int ni = 0; ni < 4; ni++) {
                    mma16816(acc[mi][ni], ah[mi], bh[ni]);  // hi*hi
                    mma16816(acc[mi][ni], ah[mi], bl[ni]);  // hi*lo
                    mma16816(acc[mi][ni], al[mi], bh[ni]);  // lo*hi
                }
        }
        __syncthreads();
    }

    // ---------------- epilogue ----------------
    float sa0 = 0.f, sb0 = 0.f, sc0 = 0.f;
    if (EPI == 3) { sa0 = *sa; sb0 = *sb; sc0 = *sc; }

    #pragma unroll
    for (int mi = 0; mi < 2; mi++) {
        const int mA = m0 + wm + mi * 16 + g;
        const int mB = mA + 8;
        float dA = 0.f, dB = 0.f;
        if (EPI == 1) { dA = deg[mA]; dB = deg[mB]; }
        #pragma unroll
        for (int ni = 0; ni < 4; ni++) {
            const int n = n0 + wn + ni * 8 + 2 * t4;
            float c0 = acc[mi][ni][0], c1 = acc[mi][ni][1];
            float c2 = acc[mi][ni][2], c3 = acc[mi][ni][3];
            if (EPI == 1) {
                c0 /= dA; c1 /= dA; c2 /= dB; c3 /= dB;
                c0 = (c0 > 0.f) ? c0 : 0.01f * c0;
                c1 = (c1 > 0.f) ? c1 : 0.01f * c1;
                c2 = (c2 > 0.f) ? c2 : 0.01f * c2;
                c3 = (c3 > 0.f) ? c3 : 0.01f * c3;
                const int e = n & 127;
                const size_t base = (size_t)(n >> 7) * ((size_t)NN * EMB) + e;
                *(float2*)&C[base + (size_t)mA * EMB] = make_float2(c0, c1);
                *(float2*)&C[base + (size_t)mB * EMB] = make_float2(c2, c3);
                if (OH != nullptr && (n >> 7) == KL - 1) {
                    __align__(4) __nv_bfloat16 h2[2], l2[2];
                    h2[0] = __float2bfloat16(c0);
                    l2[0] = __float2bfloat16(c0 - __bfloat162float(h2[0]));
                    h2[1] = __float2bfloat16(c1);
                    l2[1] = __float2bfloat16(c1 - __bfloat162float(h2[1]));
                    *(uint32_t*)&OH[(size_t)mA * EMB + e] = *(uint32_t*)h2;
                    *(uint32_t*)&OL[(size_t)mA * EMB + e] = *(uint32_t*)l2;
                    h2[0] = __float2bfloat16(c2);
                    l2[0] = __float2bfloat16(c2 - __bfloat162float(h2[0]));
                    h2[1] = __float2bfloat16(c3);
                    l2[1] = __float2bfloat16(c3 - __bfloat162float(h2[1]));
                    *(uint32_t*)&OH[(size_t)mB * EMB + e] = *(uint32_t*)h2;
                    *(uint32_t*)&OL[(size_t)mB * EMB + e] = *(uint32_t*)l2;
                }
            } else { // EPI == 3
                float2 d0 = *(const float2*)&dist[(size_t)mA * NN + n];
                float2 d1 = *(const float2*)&dist[(size_t)mB * NN + n];
                float f0 = sa0 * __powf(d0.x, sb0) * __expf(sc0 * d0.x);
                float f1 = sa0 * __powf(d0.y, sb0) * __expf(sc0 * d0.y);
                float f2 = sa0 * __powf(d1.x, sb0) * __expf(sc0 * d1.x);
                float f3 = sa0 * __powf(d1.y, sb0) * __expf(sc0 * d1.y);
                *(float2*)&C[(size_t)mA * NN + n] = make_float2(c0 * f0, c1 * f1);
                *(float2*)&C[(size_t)mB * NN + n] = make_float2(c2 * f2, c3 * f3);
            }
        }
    }
}

// ---------------- launcher ----------------
extern "C" void kernel_launch(void* const* d_in, const int* in_sizes, int n_in,
                              void* d_out, int out_size)
{
    const float* p    = (const float*)d_in[0];
    const float* q    = (const float*)d_in[1];
    const float* A    = (const float*)d_in[2];
    const float* dist = (const float*)d_in[3];
    const float* Ws   = (const float*)d_in[4];
    const float* bs   = (const float*)d_in[5];
    const float* Wd   = (const float*)d_in[6];
    const float* bd   = (const float*)d_in[7];
    const float* a    = (const float*)d_in[8];
    const float* b    = (const float*)d_in[9];
    const float* c    = (const float*)d_in[10];

    float* out   = (float*)d_out;
    float* out_p = out;
    float* out_q = out   + (size_t)KL * NN * EMB;
    float* out_e = out_q + (size_t)KL * NN * EMB;

    __nv_bfloat16 *ahi, *alo, *athi, *atlo, *wph, *wpl, *wqh, *wql, *dch, *dcl, *qh, *ql;
    float *dout, *din;
    cudaGetSymbolAddress((void**)&ahi,  g_Ahi);
    cudaGetSymbolAddress((void**)&alo,  g_Alo);
    cudaGetSymbolAddress((void**)&athi, g_AThi);
    cudaGetSymbolAddress((void**)&atlo, g_ATlo);
    cudaGetSymbolAddress((void**)&wph,  g_Wph);
    cudaGetSymbolAddress((void**)&wpl,  g_Wpl);
    cudaGetSymbolAddress((void**)&wqh,  g_Wqh);
    cudaGetSymbolAddress((void**)&wql,  g_Wql);
    cudaGetSymbolAddress((void**)&dch,  g_dech);
    cudaGetSymbolAddress((void**)&dcl,  g_decl);
    cudaGetSymbolAddress((void**)&qh,   g_qh);
    cudaGetSymbolAddress((void**)&ql,   g_ql);
    cudaGetSymbolAddress((void**)&dout, g_Dout);
    cudaGetSymbolAddress((void**)&din,  g_Din);

    cudaFuncSetAttribute(mma_gemm<1>, cudaFuncAttributeMaxDynamicSharedMemorySize, SMEM_BYTES);
    cudaFuncSetAttribute(mma_gemm<3>, cudaFuncAttributeMaxDynamicSharedMemorySize, SMEM_BYTES);

    // degrees + split + transpose in one pass over A
    zero_deg_kernel<<<NN / 256, 256>>>();
    prep_kernel<<<dim3(NN / 64, NN / 64), 256>>>(A);

    // projections -> transposed bf16 hi/lo [NKE][NN]
    sgemm_small<0><<<dim3(NKE / 64, NN / 64), 256>>>(p, Ws, EMB, bs, wph, wpl);
    sgemm_small<0><<<dim3(NKE / 64, NN / 64), 256>>>(q, Ws, EMB, bs, wqh, wql);

    // p_k = leaky_relu( (A^T @ Wp) / D_out[j] )  -> out_p [K,N,D]
    mma_gemm<1><<<dim3(NKE / 64, NN / 128), 256, SMEM_BYTES>>>(
        athi, atlo, NN, wph, wpl, NN, out_p, NN,
        dout, nullptr, nullptr, nullptr, nullptr, nullptr, nullptr);

    // q_k = leaky_relu( (A @ Wq) / D_in[j] )     -> out_q [K,N,D]; also split q_k[-1]
    mma_gemm<1><<<dim3(NKE / 64, NN / 128), 256, SMEM_BYTES>>>(
        ahi, alo, NN, wqh, wql, NN, out_q, NN,
        din, nullptr, nullptr, nullptr, nullptr, qh, ql);

    // dec = p_k[-1] @ Wd^T + bd -> bf16 hi/lo
    const float* pk2 = out_p + (size_t)(KL - 1) * NN * EMB;
    sgemm_small<1><<<dim3(EMB / 64, NN / 64), 256>>>(pk2, Wd, EMB, bd, dch, dcl);

    // e_ij = (dec @ q_k[-1]^T) * a*d^b*exp(c*d)
    mma_gemm<3><<<dim3(NN / 64, NN / 128), 256, SMEM_BYTES>>>(
        dch, dcl, EMB, qh, ql, EMB, out_e, EMB,
        nullptr, dist, a, b, c, nullptr, nullptr);
}

// round 7
// speedup vs baseline: 3.5592x; 1.1171x over previous
#include <cuda_runtime.h>
#include <cuda_bf16.h>
#include <stdint.h>
#include <math.h>

#define NN   8192
#define EMB  128
#define KL   3
#define NKE  (KL * EMB)   // 384

// ---------------- persistent scratch (no allocations allowed) ----------------
__device__ __align__(16) __nv_bfloat16 g_Ahi [(size_t)NN * NN];
__device__ __align__(16) __nv_bfloat16 g_Alo [(size_t)NN * NN];
__device__ __align__(16) __nv_bfloat16 g_AThi[(size_t)NN * NN];
__device__ __align__(16) __nv_bfloat16 g_ATlo[(size_t)NN * NN];
__device__ __align__(16) __nv_bfloat16 g_Wph[(size_t)NKE * NN];
__device__ __align__(16) __nv_bfloat16 g_Wpl[(size_t)NKE * NN];
__device__ __align__(16) __nv_bfloat16 g_Wqh[(size_t)NKE * NN];
__device__ __align__(16) __nv_bfloat16 g_Wql[(size_t)NKE * NN];
__device__ __align__(16) __nv_bfloat16 g_dech[(size_t)NN * EMB];
__device__ __align__(16) __nv_bfloat16 g_decl[(size_t)NN * EMB];
__device__ __align__(16) __nv_bfloat16 g_qh  [(size_t)NN * EMB];
__device__ __align__(16) __nv_bfloat16 g_ql  [(size_t)NN * EMB];
__device__ float g_Dout[NN];
__device__ float g_Din [NN];

// ---------------- helpers ----------------
__device__ __forceinline__ void cp16(uint32_t dst_smem, const void* src) {
    asm volatile("cp.async.ca.shared.global [%0], [%1], 16;\n"
                 :: "r"(dst_smem), "l"(src));
}
__device__ __forceinline__ void mma16816(float* c, const uint32_t* a, const uint32_t* b) {
    asm volatile(
        "mma.sync.aligned.m16n8k16.row.col.f32.bf16.bf16.f32 "
        "{%0,%1,%2,%3}, {%4,%5,%6,%7}, {%8,%9}, {%0,%1,%2,%3};\n"
        : "+f"(c[0]), "+f"(c[1]), "+f"(c[2]), "+f"(c[3])
        : "r"(a[0]), "r"(a[1]), "r"(a[2]), "r"(a[3]), "r"(b[0]), "r"(b[1]));
}
__device__ __forceinline__ void ldsm4(uint32_t* r, uint32_t addr) {
    asm volatile("ldmatrix.sync.aligned.m8n8.x4.shared.b16 {%0,%1,%2,%3}, [%4];"
                 : "=r"(r[0]), "=r"(r[1]), "=r"(r[2]), "=r"(r[3]) : "r"(addr));
}
__device__ __forceinline__ uint32_t smem_u32(const void* p) {
    return (uint32_t)__cvta_generic_to_shared(p);
}
__device__ __forceinline__ float fast_lg2(float x) {
    float y; asm("lg2.approx.f32 %0, %1;" : "=f"(y) : "f"(x)); return y;
}
__device__ __forceinline__ float fast_ex2(float x) {
    float y; asm("ex2.approx.f32 %0, %1;" : "=f"(y) : "f"(x)); return y;
}

__global__ void zero_deg_kernel() {
    int i = blockIdx.x * blockDim.x + threadIdx.x;
    if (i < NN) { g_Dout[i] = 0.0f; g_Din[i] = 0.0f; }
}

// ---------------- prep: A -> bf16 hi/lo (row-major + transposed) + degrees ----------------
__global__ void __launch_bounds__(256) prep_kernel(const float* __restrict__ A) {
    __shared__ float tile[64][65];
    const int bi = blockIdx.y * 64;
    const int bj = blockIdx.x * 64;
    const int tid = threadIdx.x;
    const int r  = tid >> 2;
    const int cs = tid & 3;

    const float* src = A + (size_t)(bi + r) * NN + bj + cs * 16;
    float v[16];
    #pragma unroll
    for (int u = 0; u < 4; u++) {
        float4 f = *(const float4*)(src + u * 4);
        v[u*4+0] = f.x; v[u*4+1] = f.y; v[u*4+2] = f.z; v[u*4+3] = f.w;
    }
    __align__(16) __nv_bfloat16 h[16], l[16];
    float rs = 0.f;
    #pragma unroll
    for (int u = 0; u < 16; u++) {
        h[u] = __float2bfloat16(v[u]);
        l[u] = __float2bfloat16(v[u] - __bfloat162float(h[u]));
        tile[r][cs * 16 + u] = v[u];
        rs += v[u];
    }
    {
        size_t idx = (size_t)(bi + r) * NN + bj + cs * 16;
        *(uint4*)&g_Ahi[idx]     = *(uint4*)&h[0];
        *(uint4*)&g_Ahi[idx + 8] = *(uint4*)&h[8];
        *(uint4*)&g_Alo[idx]     = *(uint4*)&l[0];
        *(uint4*)&g_Alo[idx + 8] = *(uint4*)&l[8];
    }
    rs += __shfl_xor_sync(0xFFFFFFFFu, rs, 1);
    rs += __shfl_xor_sync(0xFFFFFFFFu, rs, 2);
    if (cs == 0) atomicAdd(&g_Din[bi + r], rs);

    __syncthreads();

    float csum = 0.f;
    #pragma unroll
    for (int u = 0; u < 16; u++) {
        float w = tile[cs * 16 + u][r];
        h[u] = __float2bfloat16(w);
        l[u] = __float2bfloat16(w - __bfloat162float(h[u]));
        csum += w;
    }
    {
        size_t idx = (size_t)(bj + r) * NN + bi + cs * 16;
        *(uint4*)&g_AThi[idx]     = *(uint4*)&h[0];
        *(uint4*)&g_AThi[idx + 8] = *(uint4*)&h[8];
        *(uint4*)&g_ATlo[idx]     = *(uint4*)&l[0];
        *(uint4*)&g_ATlo[idx + 8] = *(uint4*)&l[8];
    }
    csum += __shfl_xor_sync(0xFFFFFFFFu, csum, 1);
    csum += __shfl_xor_sync(0xFFFFFFFFu, csum, 2);
    if (cs == 0) atomicAdd(&g_Dout[bj + r], csum);
}

// ---------------- small fp32 GEMM (projections + dec) ----------------
template<int EPI>
__global__ void __launch_bounds__(256)
sgemm_small(const float* __restrict__ A, const float* __restrict__ B,
            int Kdim, const float* __restrict__ bias,
            __nv_bfloat16* __restrict__ OH, __nv_bfloat16* __restrict__ OL)
{
    constexpr int BM = 64, BN = 64, BK = 16;
    __shared__ float As[BK][BM + 4];
    __shared__ float Bs[BK][BN + 4];
    const int t  = threadIdx.x;
    const int tx = t & 15, ty = t >> 4;
    const int m0 = blockIdx.y * BM, n0 = blockIdx.x * BN;

    float acc[4][4];
    #pragma unroll
    for (int i = 0; i < 4; i++)
        #pragma unroll
        for (int j = 0; j < 4; j++) acc[i][j] = 0.f;

    for (int k0 = 0; k0 < Kdim; k0 += BK) {
        {
            const int mm = t >> 2, kk = (t & 3) << 2;
            float4 v = *(const float4*)&A[(size_t)(m0 + mm) * Kdim + (k0 + kk)];
            As[kk + 0][mm] = v.x; As[kk + 1][mm] = v.y;
            As[kk + 2][mm] = v.z; As[kk + 3][mm] = v.w;
        }
        {
            const int nn = t >> 2, kk = (t & 3) << 2;
            float4 v = *(const float4*)&B[(size_t)(n0 + nn) * Kdim + (k0 + kk)];
            Bs[kk + 0][nn] = v.x; Bs[kk + 1][nn] = v.y;
            Bs[kk + 2][nn] = v.z; Bs[kk + 3][nn] = v.w;
        }
        __syncthreads();
        #pragma unroll
        for (int kk = 0; kk < BK; kk++) {
            float4 av = *(const float4*)&As[kk][ty << 2];
            float4 bv = *(const float4*)&Bs[kk][tx << 2];
            float a4[4] = {av.x, av.y, av.z, av.w};
            float b4[4] = {bv.x, bv.y, bv.z, bv.w};
            #pragma unroll
            for (int i = 0; i < 4; i++)
                #pragma unroll
                for (int j = 0; j < 4; j++) acc[i][j] += a4[i] * b4[j];
        }
        __syncthreads();
    }

    if (EPI == 0) {
        #pragma unroll
        for (int j = 0; j < 4; j++) {
            const int n = n0 + (tx << 2) + j;
            const float bn = bias[n];
            __align__(8) __nv_bfloat16 h[4], l[4];
            #pragma unroll
            for (int i = 0; i < 4; i++) {
                float r = acc[i][j] + bn;
                h[i] = __float2bfloat16(r);
                l[i] = __float2bfloat16(r - __bfloat162float(h[i]));
            }
            size_t idx = (size_t)n * NN + m0 + (ty << 2);
            *(uint2*)&OH[idx] = *(uint2*)h;
            *(uint2*)&OL[idx] = *(uint2*)l;
        }
    } else {
        #pragma unroll
        for (int i = 0; i < 4; i++) {
            const int m = m0 + (ty << 2) + i;
            const int n = n0 + (tx << 2);
            __align__(8) __nv_bfloat16 h[4], l[4];
            #pragma unroll
            for (int j = 0; j < 4; j++) {
                float r = acc[i][j] + bias[n + j];
                h[j] = __float2bfloat16(r);
                l[j] = __float2bfloat16(r - __bfloat162float(h[j]));
            }
            size_t idx = (size_t)m * EMB + n;
            *(uint2*)&OH[idx] = *(uint2*)h;
            *(uint2*)&OL[idx] = *(uint2*)l;
        }
    }
}

// ---------------- tensor-core split-precision GEMM (cp.async 2-stage + ldmatrix) ----------------
// C(m,n) = sum_k A(m,k)*B(n,k); A m-major [M x Kdim] (lda), B n-major [Nn x Kdim] (ldb).
// Tiles: BM=128, BN=64, BK=32. Rows stored at 80B stride (40 bf16) - conflict-free LDSM.
// EPI 1: v/deg[m], leaky_relu, store [K,N,D] remap; if OH!=null and layer==KL-1,
//        also store bf16 hi/lo at OH/OL[m*EMB + (n&127)].
// EPI 3: v * a*exp2(b*lg2(d)+c*d*log2e), d = dist[m*NN+n], store C[m*NN+n].
#define STG_STRIDE 30720
#define SMEM_BYTES (2 * STG_STRIDE)

template<int EPI>
__global__ void __launch_bounds__(256)
mma_gemm(const __nv_bfloat16* __restrict__ Ah, const __nv_bfloat16* __restrict__ Al, int lda,
         const __nv_bfloat16* __restrict__ Bh, const __nv_bfloat16* __restrict__ Bl, int ldb,
         float* __restrict__ C, int Kdim,
         const float* __restrict__ deg,
         const float* __restrict__ dist,
         const float* __restrict__ sa, const float* __restrict__ sb,
         const float* __restrict__ sc,
         __nv_bfloat16* __restrict__ OH, __nv_bfloat16* __restrict__ OL)
{
    extern __shared__ __align__(16) char smem[];
    const uint32_t sbase = smem_u32(smem);

    const int tid  = threadIdx.x;
    const int wid  = tid >> 5, lane = tid & 31;
    const int g    = lane >> 2, t4 = lane & 3;
    const int wm   = (wid >> 1) * 32;   // 4 warps in m (128)
    const int wn   = (wid & 1) * 32;    // 2 warps in n (64)
    const int m0   = blockIdx.y * 128;
    const int n0   = blockIdx.x * 64;

    // cp.async coordinates
    const int arow0 = tid >> 2;
    const int aseg  = (tid & 3) * 16;
    const int asege = (tid & 3) * 8;

    // ldmatrix lane coordinates (byte offsets within a tile of 80B rows)
    // A 16x16 fragment: mat0=(r,kb) mat1=(r+8,kb) mat2=(r,kb+8) mat3=(r+8,kb+8)
    const uint32_t aoff = (uint32_t)((wm + (lane & 7) + ((lane >> 3) & 1) * 8) * 80
                                     + (lane >> 4) * 16);
    // B pair of n8k16 fragments: mat0=(nr,kb) mat1=(nr,kb+8) mat2=(nr+8,kb) mat3=(nr+8,kb+8)
    const uint32_t boff = (uint32_t)((wn + (lane & 7) + ((lane >> 4) << 3)) * 80
                                     + ((lane >> 3) & 1) * 16);

    float acc[2][4][4];
    #pragma unroll
    for (int mi = 0; mi < 2; mi++)
        #pragma unroll
        for (int ni = 0; ni < 4; ni++)
            #pragma unroll
            for (int r = 0; r < 4; r++) acc[mi][ni][r] = 0.f;

    const int T = Kdim / 32;

    auto issue = [&](int k0, int s) {
        uint32_t sb = sbase + s * STG_STRIDE;
        #pragma unroll
        for (int it = 0; it < 2; it++) {
            int row = arow0 + it * 64;
            uint32_t dst = sb + row * 80 + aseg;
            cp16(dst,         &Ah[(size_t)(m0 + row) * lda + k0 + asege]);
            cp16(dst + 10240, &Al[(size_t)(m0 + row) * lda + k0 + asege]);
        }
        {
            int row = arow0;
            uint32_t dst = sb + 20480 + row * 80 + aseg;
            cp16(dst,        &Bh[(size_t)(n0 + row) * ldb + k0 + asege]);
            cp16(dst + 5120, &Bl[(size_t)(n0 + row) * ldb + k0 + asege]);
        }
        asm volatile("cp.async.commit_group;\n" ::: "memory");
    };

    issue(0, 0);

    for (int it = 0; it < T; it++) {
        if (it + 1 < T) {
            issue((it + 1) * 32, (it + 1) & 1);
            asm volatile("cp.async.wait_group 1;\n" ::: "memory");
        } else {
            asm volatile("cp.async.wait_group 0;\n" ::: "memory");
        }
        __syncthreads();

        const uint32_t sb  = sbase + (uint32_t)(it & 1) * STG_STRIDE;
        const uint32_t uAh = sb + aoff;
        const uint32_t uAl = sb + 10240 + aoff;
        const uint32_t uBh = sb + 20480 + boff;
        const uint32_t uBl = sb + 25600 + boff;

        #pragma unroll
        for (int kk = 0; kk < 32; kk += 16) {
            const uint32_t kb = (uint32_t)(kk * 2);   // bytes
            uint32_t ah[2][4], al[2][4], bh[4][2], bl[4][2];
            #pragma unroll
            for (int mi = 0; mi < 2; mi++) {
                ldsm4(ah[mi], uAh + (uint32_t)(mi * 16 * 80) + kb);
                ldsm4(al[mi], uAl + (uint32_t)(mi * 16 * 80) + kb);
            }
            #pragma unroll
            for (int p = 0; p < 2; p++) {
                ldsm4(&bh[2 * p][0], uBh + (uint32_t)(p * 16 * 80) + kb);
                ldsm4(&bl[2 * p][0], uBl + (uint32_t)(p * 16 * 80) + kb);
            }
            #pragma unroll
            for (int mi = 0; mi < 2; mi++)
                #pragma unroll
                for (int ni = 0; ni < 4; ni++) {
                    mma16816(acc[mi][ni], ah[mi], bh[ni]);
                    mma16816(acc[mi][ni], ah[mi], bl[ni]);
                    mma16816(acc[mi][ni], al[mi], bh[ni]);
                }
        }
        __syncthreads();
    }

    // ---------------- epilogue ----------------
    float sa0 = 0.f, sb0 = 0.f, sc0 = 0.f;
    if (EPI == 3) { sa0 = *sa; sb0 = *sb; sc0 = *sc * 1.44269504f; }

    #pragma unroll
    for (int mi = 0; mi < 2; mi++) {
        const int mA = m0 + wm + mi * 16 + g;
        const int mB = mA + 8;
        float dA = 0.f, dB = 0.f;
        if (EPI == 1) { dA = deg[mA]; dB = deg[mB]; }
        #pragma unroll
        for (int ni = 0; ni < 4; ni++) {
            const int n = n0 + wn + ni * 8 + 2 * t4;
            float c0 = acc[mi][ni][0], c1 = acc[mi][ni][1];
            float c2 = acc[mi][ni][2], c3 = acc[mi][ni][3];
            if (EPI == 1) {
                c0 /= dA; c1 /= dA; c2 /= dB; c3 /= dB;
                c0 = (c0 > 0.f) ? c0 : 0.01f * c0;
                c1 = (c1 > 0.f) ? c1 : 0.01f * c1;
                c2 = (c2 > 0.f) ? c2 : 0.01f * c2;
                c3 = (c3 > 0.f) ? c3 : 0.01f * c3;
                const int e = n & 127;
                const size_t base = (size_t)(n >> 7) * ((size_t)NN * EMB) + e;
                *(float2*)&C[base + (size_t)mA * EMB] = make_float2(c0, c1);
                *(float2*)&C[base + (size_t)mB * EMB] = make_float2(c2, c3);
                if (OH != nullptr && (n >> 7) == KL - 1) {
                    __align__(4) __nv_bfloat16 h2[2], l2[2];
                    h2[0] = __float2bfloat16(c0);
                    l2[0] = __float2bfloat16(c0 - __bfloat162float(h2[0]));
                    h2[1] = __float2bfloat16(c1);
                    l2[1] = __float2bfloat16(c1 - __bfloat162float(h2[1]));
                    *(uint32_t*)&OH[(size_t)mA * EMB + e] = *(uint32_t*)h2;
                    *(uint32_t*)&OL[(size_t)mA * EMB + e] = *(uint32_t*)l2;
                    h2[0] = __float2bfloat16(c2);
                    l2[0] = __float2bfloat16(c2 - __bfloat162float(h2[0]));
                    h2[1] = __float2bfloat16(c3);
                    l2[1] = __float2bfloat16(c3 - __bfloat162float(h2[1]));
                    *(uint32_t*)&OH[(size_t)mB * EMB + e] = *(uint32_t*)h2;
                    *(uint32_t*)&OL[(size_t)mB * EMB + e] = *(uint32_t*)l2;
                }
            } else { // EPI == 3
                float2 d0 = *(const float2*)&dist[(size_t)mA * NN + n];
                float2 d1 = *(const float2*)&dist[(size_t)mB * NN + n];
                float f0 = sa0 * fast_ex2(sb0 * fast_lg2(d0.x) + sc0 * d0.x);
                float f1 = sa0 * fast_ex2(sb0 * fast_lg2(d0.y) + sc0 * d0.y);
                float f2 = sa0 * fast_ex2(sb0 * fast_lg2(d1.x) + sc0 * d1.x);
                float f3 = sa0 * fast_ex2(sb0 * fast_lg2(d1.y) + sc0 * d1.y);
                *(float2*)&C[(size_t)mA * NN + n] = make_float2(c0 * f0, c1 * f1);
                *(float2*)&C[(size_t)mB * NN + n] = make_float2(c2 * f2, c3 * f3);
            }
        }
    }
}

// ---------------- launcher ----------------
extern "C" void kernel_launch(void* const* d_in, const int* in_sizes, int n_in,
                              void* d_out, int out_size)
{
    const float* p    = (const float*)d_in[0];
    const float* q    = (const float*)d_in[1];
    const float* A    = (const float*)d_in[2];
    const float* dist = (const float*)d_in[3];
    const float* Ws   = (const float*)d_in[4];
    const float* bs   = (const float*)d_in[5];
    const float* Wd   = (const float*)d_in[6];
    const float* bd   = (const float*)d_in[7];
    const float* a    = (const float*)d_in[8];
    const float* b    = (const float*)d_in[9];
    const float* c    = (const float*)d_in[10];

    float* out   = (float*)d_out;
    float* out_p = out;
    float* out_q = out   + (size_t)KL * NN * EMB;
    float* out_e = out_q + (size_t)KL * NN * EMB;

    __nv_bfloat16 *ahi, *alo, *athi, *atlo, *wph, *wpl, *wqh, *wql, *dch, *dcl, *qh, *ql;
    float *dout, *din;
    cudaGetSymbolAddress((void**)&ahi,  g_Ahi);
    cudaGetSymbolAddress((void**)&alo,  g_Alo);
    cudaGetSymbolAddress((void**)&athi, g_AThi);
    cudaGetSymbolAddress((void**)&atlo, g_ATlo);
    cudaGetSymbolAddress((void**)&wph,  g_Wph);
    cudaGetSymbolAddress((void**)&wpl,  g_Wpl);
    cudaGetSymbolAddress((void**)&wqh,  g_Wqh);
    cudaGetSymbolAddress((void**)&wql,  g_Wql);
    cudaGetSymbolAddress((void**)&dch,  g_dech);
    cudaGetSymbolAddress((void**)&dcl,  g_decl);
    cudaGetSymbolAddress((void**)&qh,   g_qh);
    cudaGetSymbolAddress((void**)&ql,   g_ql);
    cudaGetSymbolAddress((void**)&dout, g_Dout);
    cudaGetSymbolAddress((void**)&din,  g_Din);

    cudaFuncSetAttribute(mma_gemm<1>, cudaFuncAttributeMaxDynamicSharedMemorySize, SMEM_BYTES);
    cudaFuncSetAttribute(mma_gemm<3>, cudaFuncAttributeMaxDynamicSharedMemorySize, SMEM_BYTES);

    // degrees + split + transpose in one pass over A
    zero_deg_kernel<<<NN / 256, 256>>>();
    prep_kernel<<<dim3(NN / 64, NN / 64), 256>>>(A);

    // projections -> transposed bf16 hi/lo [NKE][NN]
    sgemm_small<0><<<dim3(NKE / 64, NN / 64), 256>>>(p, Ws, EMB, bs, wph, wpl);
    sgemm_small<0><<<dim3(NKE / 64, NN / 64), 256>>>(q, Ws, EMB, bs, wqh, wql);

    // p_k = leaky_relu( (A^T @ Wp) / D_out[j] )  -> out_p [K,N,D]
    mma_gemm<1><<<dim3(NKE / 64, NN / 128), 256, SMEM_BYTES>>>(
        athi, atlo, NN, wph, wpl, NN, out_p, NN,
        dout, nullptr, nullptr, nullptr, nullptr, nullptr, nullptr);

    // q_k = leaky_relu( (A @ Wq) / D_in[j] )     -> out_q [K,N,D]; split q_k[-1]
    mma_gemm<1><<<dim3(NKE / 64, NN / 128), 256, SMEM_BYTES>>>(
        ahi, alo, NN, wqh, wql, NN, out_q, NN,
        din, nullptr, nullptr, nullptr, nullptr, qh, ql);

    // dec = p_k[-1] @ Wd^T + bd -> bf16 hi/lo
    const float* pk2 = out_p + (size_t)(KL - 1) * NN * EMB;
    sgemm_small<1><<<dim3(EMB / 64, NN / 64), 256>>>(pk2, Wd, EMB, bd, dch, dcl);

    // e_ij = (dec @ q_k[-1]^T) * a * d^b * exp(c*d)
    mma_gemm<3><<<dim3(NN / 64, NN / 128), 256, SMEM_BYTES>>>(
        dch, dcl, EMB, qh, ql, EMB, out_e, EMB,
        nullptr, dist, a, b, c, nullptr, nullptr);
}

// round 8
// speedup vs baseline: 5.4535x; 1.5322x over previous
#include <cuda_runtime.h>
#include <cuda_fp16.h>
#include <stdint.h>
#include <math.h>

#define NN   8192
#define EMB  128
#define KL   3
#define NKE  (KL * EMB)   // 384

// ---------------- persistent scratch (no allocations allowed) ----------------
__device__ __align__(16) __half g_Ah [(size_t)NN * NN];   // A row-major fp16 hi
__device__ __align__(16) __half g_ATh[(size_t)NN * NN];   // A^T fp16 hi
__device__ __align__(16) __half g_Wph[(size_t)NKE * NN];  // Wp^T hi
__device__ __align__(16) __half g_Wpl[(size_t)NKE * NN];  // Wp^T lo
__device__ __align__(16) __half g_Wqh[(size_t)NKE * NN];
__device__ __align__(16) __half g_Wql[(size_t)NKE * NN];
__device__ __align__(16) __half g_dech[(size_t)NN * EMB];
__device__ __align__(16) __half g_qh  [(size_t)NN * EMB];
__device__ float g_Dout[NN];
__device__ float g_Din [NN];

// ---------------- helpers ----------------
__device__ __forceinline__ void cp16(uint32_t dst_smem, const void* src) {
    asm volatile("cp.async.ca.shared.global [%0], [%1], 16;\n"
                 :: "r"(dst_smem), "l"(src));
}
__device__ __forceinline__ void mma16816(float* c, const uint32_t* a, const uint32_t* b) {
    asm volatile(
        "mma.sync.aligned.m16n8k16.row.col.f32.f16.f16.f32 "
        "{%0,%1,%2,%3}, {%4,%5,%6,%7}, {%8,%9}, {%0,%1,%2,%3};\n"
        : "+f"(c[0]), "+f"(c[1]), "+f"(c[2]), "+f"(c[3])
        : "r"(a[0]), "r"(a[1]), "r"(a[2]), "r"(a[3]), "r"(b[0]), "r"(b[1]));
}
__device__ __forceinline__ void ldsm4(uint32_t* r, uint32_t addr) {
    asm volatile("ldmatrix.sync.aligned.m8n8.x4.shared.b16 {%0,%1,%2,%3}, [%4];"
                 : "=r"(r[0]), "=r"(r[1]), "=r"(r[2]), "=r"(r[3]) : "r"(addr));
}
__device__ __forceinline__ uint32_t smem_u32(const void* p) {
    return (uint32_t)__cvta_generic_to_shared(p);
}
__device__ __forceinline__ float fast_lg2(float x) {
    float y; asm("lg2.approx.f32 %0, %1;" : "=f"(y) : "f"(x)); return y;
}
__device__ __forceinline__ float fast_ex2(float x) {
    float y; asm("ex2.approx.f32 %0, %1;" : "=f"(y) : "f"(x)); return y;
}

__global__ void zero_deg_kernel() {
    int i = blockIdx.x * blockDim.x + threadIdx.x;
    if (i < NN) { g_Dout[i] = 0.0f; g_Din[i] = 0.0f; }
}

// ---------------- prep: A -> fp16 (row-major + transposed) + degrees ----------------
__global__ void __launch_bounds__(256) prep_kernel(const float* __restrict__ A) {
    __shared__ float tile[64][65];
    const int bi = blockIdx.y * 64;
    const int bj = blockIdx.x * 64;
    const int tid = threadIdx.x;
    const int r  = tid >> 2;
    const int cs = tid & 3;

    const float* src = A + (size_t)(bi + r) * NN + bj + cs * 16;
    float v[16];
    #pragma unroll
    for (int u = 0; u < 4; u++) {
        float4 f = *(const float4*)(src + u * 4);
        v[u*4+0] = f.x; v[u*4+1] = f.y; v[u*4+2] = f.z; v[u*4+3] = f.w;
    }
    __align__(16) __half h[16];
    float rs = 0.f;
    #pragma unroll
    for (int u = 0; u < 16; u++) {
        h[u] = __float2half_rn(v[u]);
        tile[r][cs * 16 + u] = v[u];
        rs += v[u];
    }
    {
        size_t idx = (size_t)(bi + r) * NN + bj + cs * 16;
        *(uint4*)&g_Ah[idx]     = *(uint4*)&h[0];
        *(uint4*)&g_Ah[idx + 8] = *(uint4*)&h[8];
    }
    rs += __shfl_xor_sync(0xFFFFFFFFu, rs, 1);
    rs += __shfl_xor_sync(0xFFFFFFFFu, rs, 2);
    if (cs == 0) atomicAdd(&g_Din[bi + r], rs);

    __syncthreads();

    float csum = 0.f;
    #pragma unroll
    for (int u = 0; u < 16; u++) {
        float w = tile[cs * 16 + u][r];
        h[u] = __float2half_rn(w);
        csum += w;
    }
    {
        size_t idx = (size_t)(bj + r) * NN + bi + cs * 16;
        *(uint4*)&g_ATh[idx]     = *(uint4*)&h[0];
        *(uint4*)&g_ATh[idx + 8] = *(uint4*)&h[8];
    }
    csum += __shfl_xor_sync(0xFFFFFFFFu, csum, 1);
    csum += __shfl_xor_sync(0xFFFFFFFFu, csum, 2);
    if (cs == 0) atomicAdd(&g_Dout[bj + r], csum);
}

// ---------------- small fp32 GEMM (projections + dec) ----------------
// EPI 0 (proj): +bias[n], store TRANSPOSED fp16 hi/lo at OH/OL[n*NN + m]
// EPI 1 (dec):  +bias[n], store row-major fp16 hi only at OH[m*EMB + n]
template<int EPI>
__global__ void __launch_bounds__(256)
sgemm_small(const float* __restrict__ A, const float* __restrict__ B,
            int Kdim, const float* __restrict__ bias,
            __half* __restrict__ OH, __half* __restrict__ OL)
{
    constexpr int BM = 64, BN = 64, BK = 16;
    __shared__ float As[BK][BM + 4];
    __shared__ float Bs[BK][BN + 4];
    const int t  = threadIdx.x;
    const int tx = t & 15, ty = t >> 4;
    const int m0 = blockIdx.y * BM, n0 = blockIdx.x * BN;

    float acc[4][4];
    #pragma unroll
    for (int i = 0; i < 4; i++)
        #pragma unroll
        for (int j = 0; j < 4; j++) acc[i][j] = 0.f;

    for (int k0 = 0; k0 < Kdim; k0 += BK) {
        {
            const int mm = t >> 2, kk = (t & 3) << 2;
            float4 v = *(const float4*)&A[(size_t)(m0 + mm) * Kdim + (k0 + kk)];
            As[kk + 0][mm] = v.x; As[kk + 1][mm] = v.y;
            As[kk + 2][mm] = v.z; As[kk + 3][mm] = v.w;
        }
        {
            const int nn = t >> 2, kk = (t & 3) << 2;
            float4 v = *(const float4*)&B[(size_t)(n0 + nn) * Kdim + (k0 + kk)];
            Bs[kk + 0][nn] = v.x; Bs[kk + 1][nn] = v.y;
            Bs[kk + 2][nn] = v.z; Bs[kk + 3][nn] = v.w;
        }
        __syncthreads();
        #pragma unroll
        for (int kk = 0; kk < BK; kk++) {
            float4 av = *(const float4*)&As[kk][ty << 2];
            float4 bv = *(const float4*)&Bs[kk][tx << 2];
            float a4[4] = {av.x, av.y, av.z, av.w};
            float b4[4] = {bv.x, bv.y, bv.z, bv.w};
            #pragma unroll
            for (int i = 0; i < 4; i++)
                #pragma unroll
                for (int j = 0; j < 4; j++) acc[i][j] += a4[i] * b4[j];
        }
        __syncthreads();
    }

    if (EPI == 0) {
        #pragma unroll
        for (int j = 0; j < 4; j++) {
            const int n = n0 + (tx << 2) + j;
            const float bn = bias[n];
            __align__(8) __half h[4], l[4];
            #pragma unroll
            for (int i = 0; i < 4; i++) {
                float r = acc[i][j] + bn;
                h[i] = __float2half_rn(r);
                l[i] = __float2half_rn(r - __half2float(h[i]));
            }
            size_t idx = (size_t)n * NN + m0 + (ty << 2);
            *(uint2*)&OH[idx] = *(uint2*)h;
            *(uint2*)&OL[idx] = *(uint2*)l;
        }
    } else {
        #pragma unroll
        for (int i = 0; i < 4; i++) {
            const int m = m0 + (ty << 2) + i;
            const int n = n0 + (tx << 2);
            __align__(8) __half h[4];
            #pragma unroll
            for (int j = 0; j < 4; j++)
                h[j] = __float2half_rn(acc[i][j] + bias[n + j]);
            *(uint2*)&OH[(size_t)m * EMB + n] = *(uint2*)h;
        }
    }
}

// ---------------- tensor-core fp16 GEMM (cp.async 2-stage + ldmatrix) ----------------
// C(m,n) = sum_k A(m,k)*B(n,k); A m-major single fp16; B n-major.
// EPI 1 (2-pass): B = Bh + Bl;  v/deg[m], leaky_relu, store [K,N,D] remap;
//                 if OH!=null and layer==KL-1, store fp16 at OH[m*EMB + (n&127)].
// EPI 3 (1-pass): B = Bh only;  v * a*exp2(b*lg2(d)+c*d*log2e), store C[m*NN+n].
template<int EPI>
__global__ void __launch_bounds__(256)
mma_gemm(const __half* __restrict__ Ah, int lda,
         const __half* __restrict__ Bh, const __half* __restrict__ Bl, int ldb,
         float* __restrict__ C, int Kdim,
         const float* __restrict__ deg,
         const float* __restrict__ dist,
         const float* __restrict__ sa, const float* __restrict__ sb,
         const float* __restrict__ sc,
         __half* __restrict__ OH)
{
    constexpr bool BLO = (EPI == 1);
    constexpr uint32_t STG = BLO ? 20480u : 15360u;

    extern __shared__ __align__(16) char smem[];
    const uint32_t sbase = smem_u32(smem);

    const int tid  = threadIdx.x;
    const int wid  = tid >> 5, lane = tid & 31;
    const int g    = lane >> 2, t4 = lane & 3;
    const int wm   = (wid >> 1) * 32;   // 4 warps in m (128)
    const int wn   = (wid & 1) * 32;    // 2 warps in n (64)
    const int m0   = blockIdx.y * 128;
    const int n0   = blockIdx.x * 64;

    const int arow0 = tid >> 2;
    const int aseg  = (tid & 3) * 16;
    const int asege = (tid & 3) * 8;

    const uint32_t aoff = (uint32_t)((wm + (lane & 7) + ((lane >> 3) & 1) * 8) * 80
                                     + (lane >> 4) * 16);
    const uint32_t boff = (uint32_t)((wn + (lane & 7) + ((lane >> 4) << 3)) * 80
                                     + ((lane >> 3) & 1) * 16);

    float acc[2][4][4];
    #pragma unroll
    for (int mi = 0; mi < 2; mi++)
        #pragma unroll
        for (int ni = 0; ni < 4; ni++)
            #pragma unroll
            for (int r = 0; r < 4; r++) acc[mi][ni][r] = 0.f;

    const int T = Kdim / 32;

    auto issue = [&](int k0, int s) {
        uint32_t sb = sbase + s * STG;
        #pragma unroll
        for (int it = 0; it < 2; it++) {
            int row = arow0 + it * 64;
            cp16(sb + row * 80 + aseg, &Ah[(size_t)(m0 + row) * lda + k0 + asege]);
        }
        {
            int row = arow0;
            uint32_t dst = sb + 10240 + row * 80 + aseg;
            cp16(dst, &Bh[(size_t)(n0 + row) * ldb + k0 + asege]);
            if (BLO)
                cp16(dst + 5120, &Bl[(size_t)(n0 + row) * ldb + k0 + asege]);
        }
        asm volatile("cp.async.commit_group;\n" ::: "memory");
    };

    issue(0, 0);

    for (int it = 0; it < T; it++) {
        if (it + 1 < T) {
            issue((it + 1) * 32, (it + 1) & 1);
            asm volatile("cp.async.wait_group 1;\n" ::: "memory");
        } else {
            asm volatile("cp.async.wait_group 0;\n" ::: "memory");
        }
        __syncthreads();

        const uint32_t sb  = sbase + (uint32_t)(it & 1) * STG;
        const uint32_t uA  = sb + aoff;
        const uint32_t uBh = sb + 10240 + boff;
        const uint32_t uBl = sb + 15360 + boff;

        #pragma unroll
        for (int kk = 0; kk < 32; kk += 16) {
            const uint32_t kb = (uint32_t)(kk * 2);
            uint32_t ah[2][4], bh[4][2], bl[4][2];
            #pragma unroll
            for (int mi = 0; mi < 2; mi++)
                ldsm4(ah[mi], uA + (uint32_t)(mi * 16 * 80) + kb);
            #pragma unroll
            for (int p = 0; p < 2; p++) {
                ldsm4(&bh[2 * p][0], uBh + (uint32_t)(p * 16 * 80) + kb);
                if (BLO) ldsm4(&bl[2 * p][0], uBl + (uint32_t)(p * 16 * 80) + kb);
            }
            #pragma unroll
            for (int mi = 0; mi < 2; mi++)
                #pragma unroll
                for (int ni = 0; ni < 4; ni++) {
                    mma16816(acc[mi][ni], ah[mi], bh[ni]);
                    if (BLO) mma16816(acc[mi][ni], ah[mi], bl[ni]);
                }
        }
        __syncthreads();
    }

    // ---------------- epilogue ----------------
    float sa0 = 0.f, sb0 = 0.f, sc0 = 0.f;
    if (EPI == 3) { sa0 = *sa; sb0 = *sb; sc0 = *sc * 1.44269504f; }

    #pragma unroll
    for (int mi = 0; mi < 2; mi++) {
        const int mA = m0 + wm + mi * 16 + g;
        const int mB = mA + 8;
        float dA = 0.f, dB = 0.f;
        if (EPI == 1) { dA = deg[mA]; dB = deg[mB]; }
        #pragma unroll
        for (int ni = 0; ni < 4; ni++) {
            const int n = n0 + wn + ni * 8 + 2 * t4;
            float c0 = acc[mi][ni][0], c1 = acc[mi][ni][1];
            float c2 = acc[mi][ni][2], c3 = acc[mi][ni][3];
            if (EPI == 1) {
                c0 /= dA; c1 /= dA; c2 /= dB; c3 /= dB;
                c0 = (c0 > 0.f) ? c0 : 0.01f * c0;
                c1 = (c1 > 0.f) ? c1 : 0.01f * c1;
                c2 = (c2 > 0.f) ? c2 : 0.01f * c2;
                c3 = (c3 > 0.f) ? c3 : 0.01f * c3;
                const int e = n & 127;
                const size_t base = (size_t)(n >> 7) * ((size_t)NN * EMB) + e;
                *(float2*)&C[base + (size_t)mA * EMB] = make_float2(c0, c1);
                *(float2*)&C[base + (size_t)mB * EMB] = make_float2(c2, c3);
                if (OH != nullptr && (n >> 7) == KL - 1) {
                    __align__(4) __half h2[2];
                    h2[0] = __float2half_rn(c0);
                    h2[1] = __float2half_rn(c1);
                    *(uint32_t*)&OH[(size_t)mA * EMB + e] = *(uint32_t*)h2;
                    h2[0] = __float2half_rn(c2);
                    h2[1] = __float2half_rn(c3);
                    *(uint32_t*)&OH[(size_t)mB * EMB + e] = *(uint32_t*)h2;
                }
            } else { // EPI == 3
                float2 d0 = *(const float2*)&dist[(size_t)mA * NN + n];
                float2 d1 = *(const float2*)&dist[(size_t)mB * NN + n];
                float f0 = sa0 * fast_ex2(sb0 * fast_lg2(d0.x) + sc0 * d0.x);
                float f1 = sa0 * fast_ex2(sb0 * fast_lg2(d0.y) + sc0 * d0.y);
                float f2 = sa0 * fast_ex2(sb0 * fast_lg2(d1.x) + sc0 * d1.x);
                float f3 = sa0 * fast_ex2(sb0 * fast_lg2(d1.y) + sc0 * d1.y);
                *(float2*)&C[(size_t)mA * NN + n] = make_float2(c0 * f0, c1 * f1);
                *(float2*)&C[(size_t)mB * NN + n] = make_float2(c2 * f2, c3 * f3);
            }
        }
    }
}

// ---------------- launcher ----------------
extern "C" void kernel_launch(void* const* d_in, const int* in_sizes, int n_in,
                              void* d_out, int out_size)
{
    const float* p    = (const float*)d_in[0];
    const float* q    = (const float*)d_in[1];
    const float* A    = (const float*)d_in[2];
    const float* dist = (const float*)d_in[3];
    const float* Ws   = (const float*)d_in[4];
    const float* bs   = (const float*)d_in[5];
    const float* Wd   = (const float*)d_in[6];
    const float* bd   = (const float*)d_in[7];
    const float* a    = (const float*)d_in[8];
    const float* b    = (const float*)d_in[9];
    const float* c    = (const float*)d_in[10];

    float* out   = (float*)d_out;
    float* out_p = out;
    float* out_q = out   + (size_t)KL * NN * EMB;
    float* out_e = out_q + (size_t)KL * NN * EMB;

    __half *ah, *ath, *wph, *wpl, *wqh, *wql, *dch, *qh;
    float *dout, *din;
    cudaGetSymbolAddress((void**)&ah,   g_Ah);
    cudaGetSymbolAddress((void**)&ath,  g_ATh);
    cudaGetSymbolAddress((void**)&wph,  g_Wph);
    cudaGetSymbolAddress((void**)&wpl,  g_Wpl);
    cudaGetSymbolAddress((void**)&wqh,  g_Wqh);
    cudaGetSymbolAddress((void**)&wql,  g_Wql);
    cudaGetSymbolAddress((void**)&dch,  g_dech);
    cudaGetSymbolAddress((void**)&qh,   g_qh);
    cudaGetSymbolAddress((void**)&dout, g_Dout);
    cudaGetSymbolAddress((void**)&din,  g_Din);

    // degrees + fp16 conversion + transpose in one pass over A
    zero_deg_kernel<<<NN / 256, 256>>>();
    prep_kernel<<<dim3(NN / 64, NN / 64), 256>>>(A);

    // projections -> transposed fp16 hi/lo [NKE][NN]
    sgemm_small<0><<<dim3(NKE / 64, NN / 64), 256>>>(p, Ws, EMB, bs, wph, wpl);
    sgemm_small<0><<<dim3(NKE / 64, NN / 64), 256>>>(q, Ws, EMB, bs, wqh, wql);

    // p_k = leaky_relu( (A^T @ Wp) / D_out[j] )  -> out_p [K,N,D]
    mma_gemm<1><<<dim3(NKE / 64, NN / 128), 256, 2 * 20480>>>(
        ath, NN, wph, wpl, NN, out_p, NN,
        dout, nullptr, nullptr, nullptr, nullptr, nullptr);

    // q_k = leaky_relu( (A @ Wq) / D_in[j] )     -> out_q [K,N,D]; emit q_k[-1] fp16
    mma_gemm<1><<<dim3(NKE / 64, NN / 128), 256, 2 * 20480>>>(
        ah, NN, wqh, wql, NN, out_q, NN,
        din, nullptr, nullptr, nullptr, nullptr, qh);

    // dec = p_k[-1] @ Wd^T + bd -> fp16
    const float* pk2 = out_p + (size_t)(KL - 1) * NN * EMB;
    sgemm_small<1><<<dim3(EMB / 64, NN / 64), 256>>>(pk2, Wd, EMB, bd, dch, nullptr);

    // e_ij = (dec @ q_k[-1]^T) * a * d^b * exp(c*d)   (single-pass fp16)
    mma_gemm<3><<<dim3(NN / 64, NN / 128), 256, 2 * 15360>>>(
        dch, EMB, qh, nullptr, EMB, out_e, EMB,
        nullptr, dist, a, b, c, nullptr);
}

// round 9
// speedup vs baseline: 6.8656x; 1.2589x over previous
#include <cuda_runtime.h>
#include <cuda_fp16.h>
#include <stdint.h>
#include <math.h>

#define NN   8192
#define EMB  128
#define KL   3
#define NKE  (KL * EMB)   // 384

// ---------------- persistent scratch (no allocations allowed) ----------------
__device__ __align__(16) __half g_Ah [(size_t)NN * NN];   // A row-major fp16
__device__ __align__(16) __half g_ATh[(size_t)NN * NN];   // A^T fp16
__device__ __align__(16) __half g_Wph[(size_t)NKE * NN];  // Wp^T fp16
__device__ __align__(16) __half g_Wqh[(size_t)NKE * NN];  // Wq^T fp16
__device__ __align__(16) __half g_dech[(size_t)NN * EMB];
__device__ __align__(16) __half g_qh  [(size_t)NN * EMB];
__device__ float g_Dout[NN];
__device__ float g_Din [NN];

// ---------------- helpers ----------------
__device__ __forceinline__ void cp16(uint32_t dst_smem, const void* src) {
    asm volatile("cp.async.ca.shared.global [%0], [%1], 16;\n"
                 :: "r"(dst_smem), "l"(src));
}
__device__ __forceinline__ void mma16816(float* c, const uint32_t* a, const uint32_t* b) {
    asm volatile(
        "mma.sync.aligned.m16n8k16.row.col.f32.f16.f16.f32 "
        "{%0,%1,%2,%3}, {%4,%5,%6,%7}, {%8,%9}, {%0,%1,%2,%3};\n"
        : "+f"(c[0]), "+f"(c[1]), "+f"(c[2]), "+f"(c[3])
        : "r"(a[0]), "r"(a[1]), "r"(a[2]), "r"(a[3]), "r"(b[0]), "r"(b[1]));
}
__device__ __forceinline__ void ldsm4(uint32_t* r, uint32_t addr) {
    asm volatile("ldmatrix.sync.aligned.m8n8.x4.shared.b16 {%0,%1,%2,%3}, [%4];"
                 : "=r"(r[0]), "=r"(r[1]), "=r"(r[2]), "=r"(r[3]) : "r"(addr));
}
__device__ __forceinline__ uint32_t smem_u32(const void* p) {
    return (uint32_t)__cvta_generic_to_shared(p);
}
__device__ __forceinline__ float fast_lg2(float x) {
    float y; asm("lg2.approx.f32 %0, %1;" : "=f"(y) : "f"(x)); return y;
}
__device__ __forceinline__ float fast_ex2(float x) {
    float y; asm("ex2.approx.f32 %0, %1;" : "=f"(y) : "f"(x)); return y;
}

__global__ void zero_deg_kernel() {
    int i = blockIdx.x * blockDim.x + threadIdx.x;
    if (i < NN) { g_Dout[i] = 0.0f; g_Din[i] = 0.0f; }
}

// ---------------- prep: A -> fp16 (row-major + transposed) + degrees ----------------
__global__ void __launch_bounds__(256) prep_kernel(const float* __restrict__ A) {
    __shared__ float tile[64][65];
    const int bi = blockIdx.y * 64;
    const int bj = blockIdx.x * 64;
    const int tid = threadIdx.x;
    const int r  = tid >> 2;
    const int cs = tid & 3;

    const float* src = A + (size_t)(bi + r) * NN + bj + cs * 16;
    float v[16];
    #pragma unroll
    for (int u = 0; u < 4; u++) {
        float4 f = *(const float4*)(src + u * 4);
        v[u*4+0] = f.x; v[u*4+1] = f.y; v[u*4+2] = f.z; v[u*4+3] = f.w;
    }
    __align__(16) __half h[16];
    float rs = 0.f;
    #pragma unroll
    for (int u = 0; u < 16; u++) {
        h[u] = __float2half_rn(v[u]);
        tile[r][cs * 16 + u] = v[u];
        rs += v[u];
    }
    {
        size_t idx = (size_t)(bi + r) * NN + bj + cs * 16;
        *(uint4*)&g_Ah[idx]     = *(uint4*)&h[0];
        *(uint4*)&g_Ah[idx + 8] = *(uint4*)&h[8];
    }
    rs += __shfl_xor_sync(0xFFFFFFFFu, rs, 1);
    rs += __shfl_xor_sync(0xFFFFFFFFu, rs, 2);
    if (cs == 0) atomicAdd(&g_Din[bi + r], rs);

    __syncthreads();

    float csum = 0.f;
    #pragma unroll
    for (int u = 0; u < 16; u++) {
        float w = tile[cs * 16 + u][r];
        h[u] = __float2half_rn(w);
        csum += w;
    }
    {
        size_t idx = (size_t)(bj + r) * NN + bi + cs * 16;
        *(uint4*)&g_ATh[idx]     = *(uint4*)&h[0];
        *(uint4*)&g_ATh[idx + 8] = *(uint4*)&h[8];
    }
    csum += __shfl_xor_sync(0xFFFFFFFFu, csum, 1);
    csum += __shfl_xor_sync(0xFFFFFFFFu, csum, 2);
    if (cs == 0) atomicAdd(&g_Dout[bj + r], csum);
}

// ---------------- small fp32 GEMM (projections + dec) ----------------
// EPI 0 (proj): +bias[n], store TRANSPOSED fp16 at OH[n*NN + m]
// EPI 1 (dec):  +bias[n], store row-major fp16 at OH[m*EMB + n]
template<int EPI>
__global__ void __launch_bounds__(256)
sgemm_small(const float* __restrict__ A, const float* __restrict__ B,
            int Kdim, const float* __restrict__ bias,
            __half* __restrict__ OH)
{
    constexpr int BM = 64, BN = 64, BK = 16;
    __shared__ float As[BK][BM + 4];
    __shared__ float Bs[BK][BN + 4];
    const int t  = threadIdx.x;
    const int tx = t & 15, ty = t >> 4;
    const int m0 = blockIdx.y * BM, n0 = blockIdx.x * BN;

    float acc[4][4];
    #pragma unroll
    for (int i = 0; i < 4; i++)
        #pragma unroll
        for (int j = 0; j < 4; j++) acc[i][j] = 0.f;

    for (int k0 = 0; k0 < Kdim; k0 += BK) {
        {
            const int mm = t >> 2, kk = (t & 3) << 2;
            float4 v = *(const float4*)&A[(size_t)(m0 + mm) * Kdim + (k0 + kk)];
            As[kk + 0][mm] = v.x; As[kk + 1][mm] = v.y;
            As[kk + 2][mm] = v.z; As[kk + 3][mm] = v.w;
        }
        {
            const int nn = t >> 2, kk = (t & 3) << 2;
            float4 v = *(const float4*)&B[(size_t)(n0 + nn) * Kdim + (k0 + kk)];
            Bs[kk + 0][nn] = v.x; Bs[kk + 1][nn] = v.y;
            Bs[kk + 2][nn] = v.z; Bs[kk + 3][nn] = v.w;
        }
        __syncthreads();
        #pragma unroll
        for (int kk = 0; kk < BK; kk++) {
            float4 av = *(const float4*)&As[kk][ty << 2];
            float4 bv = *(const float4*)&Bs[kk][tx << 2];
            float a4[4] = {av.x, av.y, av.z, av.w};
            float b4[4] = {bv.x, bv.y, bv.z, bv.w};
            #pragma unroll
            for (int i = 0; i < 4; i++)
                #pragma unroll
                for (int j = 0; j < 4; j++) acc[i][j] += a4[i] * b4[j];
        }
        __syncthreads();
    }

    if (EPI == 0) {
        #pragma unroll
        for (int j = 0; j < 4; j++) {
            const int n = n0 + (tx << 2) + j;
            const float bn = bias[n];
            __align__(8) __half h[4];
            #pragma unroll
            for (int i = 0; i < 4; i++)
                h[i] = __float2half_rn(acc[i][j] + bn);
            *(uint2*)&OH[(size_t)n * NN + m0 + (ty << 2)] = *(uint2*)h;
        }
    } else {
        #pragma unroll
        for (int i = 0; i < 4; i++) {
            const int m = m0 + (ty << 2) + i;
            const int n = n0 + (tx << 2);
            __align__(8) __half h[4];
            #pragma unroll
            for (int j = 0; j < 4; j++)
                h[j] = __float2half_rn(acc[i][j] + bias[n + j]);
            *(uint2*)&OH[(size_t)m * EMB + n] = *(uint2*)h;
        }
    }
}

// ---------------- tensor-core fp16 GEMM (cp.async 2-stage + ldmatrix, 1-pass) ----------------
// C(m,n) = sum_k A(m,k)*B(n,k); A m-major fp16, B n-major fp16.
// EPI 1: v/deg[m], leaky_relu, store [K,N,D] remap; if OH!=null and layer==KL-1,
//        also store fp16 at OH[m*EMB + (n&127)].
// EPI 3: v * a*exp2(b*lg2(d)+c*d*log2e), d = dist[m*NN+n], store C[m*NN+n].
#define STG 15360u
#define SMEM_BYTES (2 * 15360)

template<int EPI>
__global__ void __launch_bounds__(256)
mma_gemm(const __half* __restrict__ Ah, int lda,
         const __half* __restrict__ Bh, int ldb,
         float* __restrict__ C, int Kdim,
         const float* __restrict__ deg,
         const float* __restrict__ dist,
         const float* __restrict__ sa, const float* __restrict__ sb,
         const float* __restrict__ sc,
         __half* __restrict__ OH)
{
    extern __shared__ __align__(16) char smem[];
    const uint32_t sbase = smem_u32(smem);

    const int tid  = threadIdx.x;
    const int wid  = tid >> 5, lane = tid & 31;
    const int g    = lane >> 2, t4 = lane & 3;
    const int wm   = (wid >> 1) * 32;   // 4 warps in m (128)
    const int wn   = (wid & 1) * 32;    // 2 warps in n (64)
    const int m0   = blockIdx.y * 128;
    const int n0   = blockIdx.x * 64;

    const int arow0 = tid >> 2;
    const int aseg  = (tid & 3) * 16;
    const int asege = (tid & 3) * 8;

    const uint32_t aoff = (uint32_t)((wm + (lane & 7) + ((lane >> 3) & 1) * 8) * 80
                                     + (lane >> 4) * 16);
    const uint32_t boff = (uint32_t)((wn + (lane & 7) + ((lane >> 4) << 3)) * 80
                                     + ((lane >> 3) & 1) * 16);

    float acc[2][4][4];
    #pragma unroll
    for (int mi = 0; mi < 2; mi++)
        #pragma unroll
        for (int ni = 0; ni < 4; ni++)
            #pragma unroll
            for (int r = 0; r < 4; r++) acc[mi][ni][r] = 0.f;

    const int T = Kdim / 32;

    auto issue = [&](int k0, int s) {
        uint32_t sb = sbase + s * STG;
        #pragma unroll
        for (int it = 0; it < 2; it++) {
            int row = arow0 + it * 64;
            cp16(sb + row * 80 + aseg, &Ah[(size_t)(m0 + row) * lda + k0 + asege]);
        }
        cp16(sb + 10240 + arow0 * 80 + aseg,
             &Bh[(size_t)(n0 + arow0) * ldb + k0 + asege]);
        asm volatile("cp.async.commit_group;\n" ::: "memory");
    };

    issue(0, 0);

    for (int it = 0; it < T; it++) {
        if (it + 1 < T) {
            issue((it + 1) * 32, (it + 1) & 1);
            asm volatile("cp.async.wait_group 1;\n" ::: "memory");
        } else {
            asm volatile("cp.async.wait_group 0;\n" ::: "memory");
        }
        __syncthreads();

        const uint32_t sb  = sbase + (uint32_t)(it & 1) * STG;
        const uint32_t uA  = sb + aoff;
        const uint32_t uB  = sb + 10240 + boff;

        #pragma unroll
        for (int kk = 0; kk < 32; kk += 16) {
            const uint32_t kb = (uint32_t)(kk * 2);
            uint32_t ah[2][4], bh[4][2];
            #pragma unroll
            for (int mi = 0; mi < 2; mi++)
                ldsm4(ah[mi], uA + (uint32_t)(mi * 16 * 80) + kb);
            #pragma unroll
            for (int p = 0; p < 2; p++)
                ldsm4(&bh[2 * p][0], uB + (uint32_t)(p * 16 * 80) + kb);
            #pragma unroll
            for (int mi = 0; mi < 2; mi++)
                #pragma unroll
                for (int ni = 0; ni < 4; ni++)
                    mma16816(acc[mi][ni], ah[mi], bh[ni]);
        }
        __syncthreads();
    }

    // ---------------- epilogue ----------------
    float sa0 = 0.f, sb0 = 0.f, sc0 = 0.f;
    if (EPI == 3) { sa0 = *sa; sb0 = *sb; sc0 = *sc * 1.44269504f; }

    #pragma unroll
    for (int mi = 0; mi < 2; mi++) {
        const int mA = m0 + wm + mi * 16 + g;
        const int mB = mA + 8;
        float dA = 0.f, dB = 0.f;
        if (EPI == 1) { dA = deg[mA]; dB = deg[mB]; }
        #pragma unroll
        for (int ni = 0; ni < 4; ni++) {
            const int n = n0 + wn + ni * 8 + 2 * t4;
            float c0 = acc[mi][ni][0], c1 = acc[mi][ni][1];
            float c2 = acc[mi][ni][2], c3 = acc[mi][ni][3];
            if (EPI == 1) {
                c0 /= dA; c1 /= dA; c2 /= dB; c3 /= dB;
                c0 = (c0 > 0.f) ? c0 : 0.01f * c0;
                c1 = (c1 > 0.f) ? c1 : 0.01f * c1;
                c2 = (c2 > 0.f) ? c2 : 0.01f * c2;
                c3 = (c3 > 0.f) ? c3 : 0.01f * c3;
                const int e = n & 127;
                const size_t base = (size_t)(n >> 7) * ((size_t)NN * EMB) + e;
                *(float2*)&C[base + (size_t)mA * EMB] = make_float2(c0, c1);
                *(float2*)&C[base + (size_t)mB * EMB] = make_float2(c2, c3);
                if (OH != nullptr && (n >> 7) == KL - 1) {
                    __align__(4) __half h2[2];
                    h2[0] = __float2half_rn(c0);
                    h2[1] = __float2half_rn(c1);
                    *(uint32_t*)&OH[(size_t)mA * EMB + e] = *(uint32_t*)h2;
                    h2[0] = __float2half_rn(c2);
                    h2[1] = __float2half_rn(c3);
                    *(uint32_t*)&OH[(size_t)mB * EMB + e] = *(uint32_t*)h2;
                }
            } else { // EPI == 3
                float2 d0 = *(const float2*)&dist[(size_t)mA * NN + n];
                float2 d1 = *(const float2*)&dist[(size_t)mB * NN + n];
                float f0 = sa0 * fast_ex2(sb0 * fast_lg2(d0.x) + sc0 * d0.x);
                float f1 = sa0 * fast_ex2(sb0 * fast_lg2(d0.y) + sc0 * d0.y);
                float f2 = sa0 * fast_ex2(sb0 * fast_lg2(d1.x) + sc0 * d1.x);
                float f3 = sa0 * fast_ex2(sb0 * fast_lg2(d1.y) + sc0 * d1.y);
                *(float2*)&C[(size_t)mA * NN + n] = make_float2(c0 * f0, c1 * f1);
                *(float2*)&C[(size_t)mB * NN + n] = make_float2(c2 * f2, c3 * f3);
            }
        }
    }
}

// ---------------- launcher ----------------
extern "C" void kernel_launch(void* const* d_in, const int* in_sizes, int n_in,
                              void* d_out, int out_size)
{
    const float* p    = (const float*)d_in[0];
    const float* q    = (const float*)d_in[1];
    const float* A    = (const float*)d_in[2];
    const float* dist = (const float*)d_in[3];
    const float* Ws   = (const float*)d_in[4];
    const float* bs   = (const float*)d_in[5];
    const float* Wd   = (const float*)d_in[6];
    const float* bd   = (const float*)d_in[7];
    const float* a    = (const float*)d_in[8];
    const float* b    = (const float*)d_in[9];
    const float* c    = (const float*)d_in[10];

    float* out   = (float*)d_out;
    float* out_p = out;
    float* out_q = out   + (size_t)KL * NN * EMB;
    float* out_e = out_q + (size_t)KL * NN * EMB;

    __half *ah, *ath, *wph, *wqh, *dch, *qh;
    float *dout, *din;
    cudaGetSymbolAddress((void**)&ah,   g_Ah);
    cudaGetSymbolAddress((void**)&ath,  g_ATh);
    cudaGetSymbolAddress((void**)&wph,  g_Wph);
    cudaGetSymbolAddress((void**)&wqh,  g_Wqh);
    cudaGetSymbolAddress((void**)&dch,  g_dech);
    cudaGetSymbolAddress((void**)&qh,   g_qh);
    cudaGetSymbolAddress((void**)&dout, g_Dout);
    cudaGetSymbolAddress((void**)&din,  g_Din);

    // degrees + fp16 conversion + transpose in one pass over A
    zero_deg_kernel<<<NN / 256, 256>>>();
    prep_kernel<<<dim3(NN / 64, NN / 64), 256>>>(A);

    // projections -> transposed fp16 [NKE][NN]
    sgemm_small<0><<<dim3(NKE / 64, NN / 64), 256>>>(p, Ws, EMB, bs, wph);
    sgemm_small<0><<<dim3(NKE / 64, NN / 64), 256>>>(q, Ws, EMB, bs, wqh);

    // p_k = leaky_relu( (A^T @ Wp) / D_out[j] )  -> out_p [K,N,D]
    mma_gemm<1><<<dim3(NKE / 64, NN / 128), 256, SMEM_BYTES>>>(
        ath, NN, wph, NN, out_p, NN,
        dout, nullptr, nullptr, nullptr, nullptr, nullptr);

    // q_k = leaky_relu( (A @ Wq) / D_in[j] )     -> out_q [K,N,D]; emit q_k[-1] fp16
    mma_gemm<1><<<dim3(NKE / 64, NN / 128), 256, SMEM_BYTES>>>(
        ah, NN, wqh, NN, out_q, NN,
        din, nullptr, nullptr, nullptr, nullptr, qh);

    // dec = p_k[-1] @ Wd^T + bd -> fp16
    const float* pk2 = out_p + (size_t)(KL - 1) * NN * EMB;
    sgemm_small<1><<<dim3(EMB / 64, NN / 64), 256>>>(pk2, Wd, EMB, bd, dch);

    // e_ij = (dec @ q_k[-1]^T) * a * d^b * exp(c*d)   (single-pass fp16)
    mma_gemm<3><<<dim3(NN / 64, NN / 128), 256, SMEM_BYTES>>>(
        dch, EMB, qh, EMB, out_e, EMB,
        nullptr, dist, a, b, c, nullptr);
}